// round 1
// baseline (speedup 1.0000x reference)
#include <cuda_runtime.h>
#include <math.h>

// Problem constants: B=4, T=8192, H=512
#define B_ 4
#define T_ 8192
#define H_ 512
#define BT_ (B_ * T_)          // 32768 rows
#define CL_ 128                // scan chunk length
#define NC_ (T_ / CL_)         // 64 chunks

// ---------------------------------------------------------------------------
// Scratch (device globals; no runtime allocation allowed)
// ---------------------------------------------------------------------------
__device__ float g_ln [(size_t)BT_ * H_];   // LN output (reused for LN1 and LN2)
__device__ float g_k  [(size_t)BT_ * H_];   // raw k, then c = sigmoid(-k)
__device__ float g_v  [(size_t)BT_ * H_];   // v = z * g(preh)
__device__ float g_x2 [(size_t)BT_ * H_];   // x after first residual
__device__ float g_h1 [(size_t)BT_ * H_];   // FFN hidden
__device__ float g_A  [B_ * H_ * NC_];      // per-chunk coeff product
__device__ float g_Bv [B_ * H_ * NC_];      // per-chunk affine term
__device__ float g_hin[B_ * H_ * NC_];      // per-chunk entry state

// ---------------------------------------------------------------------------
// helpers
// ---------------------------------------------------------------------------
__device__ __forceinline__ float gfun(float x) {
    // g(x) = x + 0.5 for x >= 0 else sigmoid(x)
    return x >= 0.f ? x + 0.5f : 1.f / (1.f + expf(-x));
}

// ---------------------------------------------------------------------------
// LayerNorm: one warp per row (H=512 -> 4 float4 per lane)
// ---------------------------------------------------------------------------
__global__ __launch_bounds__(256) void ln_kernel(
    const float* __restrict__ in, const float* __restrict__ gam,
    const float* __restrict__ bet, float* __restrict__ out)
{
    const int lane = threadIdx.x & 31;
    const int row  = blockIdx.x * 8 + (threadIdx.x >> 5);
    const float4* p = (const float4*)(in + (size_t)row * H_);
    float4* q = (float4*)(out + (size_t)row * H_);

    float4 v[4];
    float s = 0.f, ss = 0.f;
#pragma unroll
    for (int i = 0; i < 4; ++i) {
        v[i] = p[lane + 32 * i];
        s  += v[i].x + v[i].y + v[i].z + v[i].w;
        ss += v[i].x * v[i].x + v[i].y * v[i].y + v[i].z * v[i].z + v[i].w * v[i].w;
    }
#pragma unroll
    for (int o = 16; o; o >>= 1) {
        s  += __shfl_xor_sync(0xffffffffu, s,  o);
        ss += __shfl_xor_sync(0xffffffffu, ss, o);
    }
    const float mu  = s * (1.f / H_);
    const float var = ss * (1.f / H_) - mu * mu;
    const float r   = rsqrtf(var + 1e-5f);
#pragma unroll
    for (int i = 0; i < 4; ++i) {
        const int c4 = lane + 32 * i;
        float4 g4 = ((const float4*)gam)[c4];
        float4 b4 = ((const float4*)bet)[c4];
        float4 o4;
        o4.x = (v[i].x - mu) * r * g4.x + b4.x;
        o4.y = (v[i].y - mu) * r * g4.y + b4.y;
        o4.z = (v[i].z - mu) * r * g4.z + b4.z;
        o4.w = (v[i].w - mu) * r * g4.w + b4.w;
        q[c4] = o4;
    }
}

// ---------------------------------------------------------------------------
// fp32 tiled GEMM: out[M=32768, N=512] = A[M,512] @ W[512,512] (+ epilogue)
// Block tile 128x64, 256 threads, 8x4 per thread.
// EPI: 0 = raw (+bias)   -> out
//      1 = gate: aux holds raw k; write c=sigmoid(-k) to aux, v=z*g(acc+b) to out
//      2 = relu(acc+bias) -> out
//      3 = acc+bias+aux   -> out (residual)
// ---------------------------------------------------------------------------
template<int EPI>
__global__ __launch_bounds__(256) void gemm_kernel(
    const float* __restrict__ A, const float* __restrict__ W,
    const float* __restrict__ bias, float* __restrict__ out,
    float* __restrict__ aux)
{
    __shared__ float As[16][128];
    __shared__ float Bs[16][64];
    const int tid = threadIdx.x;
    const int m0 = blockIdx.y * 128;
    const int n0 = blockIdx.x * 64;
    const int tx = tid & 15, ty = tid >> 4;

    float acc[8][4];
#pragma unroll
    for (int i = 0; i < 8; ++i)
#pragma unroll
        for (int j = 0; j < 4; ++j) acc[i][j] = 0.f;

    for (int k0 = 0; k0 < 512; k0 += 16) {
#pragma unroll
        for (int r = 0; r < 2; ++r) {
            const int f = tid + r * 256;
            const int row = f >> 2, cc = (f & 3) << 2;
            float4 av = *(const float4*)(A + (size_t)(m0 + row) * 512 + k0 + cc);
            As[cc + 0][row] = av.x;
            As[cc + 1][row] = av.y;
            As[cc + 2][row] = av.z;
            As[cc + 3][row] = av.w;
        }
        {
            const int row = tid >> 4, cc = (tid & 15) << 2;
            *(float4*)(&Bs[row][cc]) =
                *(const float4*)(W + (size_t)(k0 + row) * 512 + n0 + cc);
        }
        __syncthreads();
#pragma unroll
        for (int kk = 0; kk < 16; ++kk) {
            float4 a0 = *(const float4*)(&As[kk][ty * 8]);
            float4 a1 = *(const float4*)(&As[kk][ty * 8 + 4]);
            float4 bv = *(const float4*)(&Bs[kk][tx * 4]);
            const float a[8] = {a0.x, a0.y, a0.z, a0.w, a1.x, a1.y, a1.z, a1.w};
            const float b[4] = {bv.x, bv.y, bv.z, bv.w};
#pragma unroll
            for (int i = 0; i < 8; ++i)
#pragma unroll
                for (int j = 0; j < 4; ++j)
                    acc[i][j] = fmaf(a[i], b[j], acc[i][j]);
        }
        __syncthreads();
    }

    const float4 bias4 = *(const float4*)(bias + n0 + tx * 4);
#pragma unroll
    for (int i = 0; i < 8; ++i) {
        const int row = m0 + ty * 8 + i;
        const size_t o = (size_t)row * 512 + n0 + tx * 4;
        float4 r4;
        r4.x = acc[i][0] + bias4.x;
        r4.y = acc[i][1] + bias4.y;
        r4.z = acc[i][2] + bias4.z;
        r4.w = acc[i][3] + bias4.w;
        if (EPI == 0) {
            *(float4*)(out + o) = r4;
        } else if (EPI == 1) {
            float4 k4 = *(const float4*)(aux + o);
            float4 c4, v4;
            { float c = 1.f / (1.f + expf(k4.x)); c4.x = c; v4.x = (1.f - c) * gfun(r4.x); }
            { float c = 1.f / (1.f + expf(k4.y)); c4.y = c; v4.y = (1.f - c) * gfun(r4.y); }
            { float c = 1.f / (1.f + expf(k4.z)); c4.z = c; v4.z = (1.f - c) * gfun(r4.z); }
            { float c = 1.f / (1.f + expf(k4.w)); c4.w = c; v4.w = (1.f - c) * gfun(r4.w); }
            *(float4*)(aux + o) = c4;
            *(float4*)(out + o) = v4;
        } else if (EPI == 2) {
            r4.x = fmaxf(r4.x, 0.f); r4.y = fmaxf(r4.y, 0.f);
            r4.z = fmaxf(r4.z, 0.f); r4.w = fmaxf(r4.w, 0.f);
            *(float4*)(out + o) = r4;
        } else {
            float4 x4 = *(const float4*)(aux + o);
            r4.x += x4.x; r4.y += x4.y; r4.z += x4.z; r4.w += x4.w;
            *(float4*)(out + o) = r4;
        }
    }
}

// ---------------------------------------------------------------------------
// Chunked scan: h_t = c_t * h_{t-1} + v_t, h_0 = 0.5, over T per (b,h) channel.
// Phase 1: per-chunk (A = prod c, Bv = affine from 0)
// ---------------------------------------------------------------------------
__global__ __launch_bounds__(512) void scan_phase1(
    const float* __restrict__ c, const float* __restrict__ v,
    float* __restrict__ Aout, float* __restrict__ Bout)
{
    const int h  = threadIdx.x;
    const int bj = blockIdx.x;                 // b*NC + j
    const int b  = bj >> 6, j = bj & (NC_ - 1);
    size_t base = ((size_t)b * T_ + (size_t)j * CL_) * H_ + h;
    float A = 1.f, Bv = 0.f;
    for (int t = 0; t < CL_; ++t) {
        const float ct = c[base];
        const float vt = v[base];
        Bv = fmaf(ct, Bv, vt);
        A *= ct;
        base += H_;
    }
    Aout[bj * H_ + h] = A;
    Bout[bj * H_ + h] = Bv;
}

// Phase 2: sequential combine across the 64 chunk summaries per channel
__global__ __launch_bounds__(512) void scan_phase2(
    const float* __restrict__ A, const float* __restrict__ Bv,
    float* __restrict__ hin)
{
    const int h = threadIdx.x;
    const int b = blockIdx.x;
    float hr = 0.5f;
#pragma unroll
    for (int j = 0; j < NC_; ++j) {
        const int idx = (b * NC_ + j) * H_ + h;
        hin[idx] = hr;
        hr = fmaf(A[idx], hr, Bv[idx]);
    }
}

// Phase 3: recompute recurrence with correct entry state; fuse first residual
__global__ __launch_bounds__(512) void scan_phase3(
    const float* __restrict__ c, const float* __restrict__ v,
    const float* __restrict__ hin, const float* __restrict__ x,
    float* __restrict__ x2)
{
    const int h  = threadIdx.x;
    const int bj = blockIdx.x;
    const int b  = bj >> 6, j = bj & (NC_ - 1);
    size_t base = ((size_t)b * T_ + (size_t)j * CL_) * H_ + h;
    float hr = hin[bj * H_ + h];
    for (int t = 0; t < CL_; ++t) {
        hr = fmaf(c[base], hr, v[base]);
        x2[base] = x[base] + hr;
        base += H_;
    }
}

// ---------------------------------------------------------------------------
// launch
// ---------------------------------------------------------------------------
extern "C" void kernel_launch(void* const* d_in, const int* in_sizes, int n_in,
                              void* d_out, int out_size)
{
    const float* x    = (const float*)d_in[0];
    const float* ln1g = (const float*)d_in[1];
    const float* ln1b = (const float*)d_in[2];
    const float* Wz   = (const float*)d_in[3];
    const float* bz   = (const float*)d_in[4];
    const float* Wh   = (const float*)d_in[5];
    const float* bh   = (const float*)d_in[6];
    const float* ln2g = (const float*)d_in[7];
    const float* ln2b = (const float*)d_in[8];
    const float* W1   = (const float*)d_in[9];
    const float* b1   = (const float*)d_in[10];
    const float* W2   = (const float*)d_in[11];
    const float* b2   = (const float*)d_in[12];
    float* out = (float*)d_out;

    float *p_ln, *p_k, *p_v, *p_x2, *p_h1, *p_A, *p_Bv, *p_hin;
    cudaGetSymbolAddress((void**)&p_ln,  g_ln);
    cudaGetSymbolAddress((void**)&p_k,   g_k);
    cudaGetSymbolAddress((void**)&p_v,   g_v);
    cudaGetSymbolAddress((void**)&p_x2,  g_x2);
    cudaGetSymbolAddress((void**)&p_h1,  g_h1);
    cudaGetSymbolAddress((void**)&p_A,   g_A);
    cudaGetSymbolAddress((void**)&p_Bv,  g_Bv);
    cudaGetSymbolAddress((void**)&p_hin, g_hin);

    const dim3 gg(512 / 64, BT_ / 128);   // (8, 256)

    // x_ln = LN1(x)
    ln_kernel<<<BT_ / 8, 256>>>(x, ln1g, ln1b, p_ln);
    // k = x_ln @ Wz + bz (raw)
    gemm_kernel<0><<<gg, 256>>>(p_ln, Wz, bz, p_k, nullptr);
    // preh = x_ln @ Wh + bh ; c = sigmoid(-k) -> g_k ; v = sigmoid(k)*g(preh) -> g_v
    gemm_kernel<1><<<gg, 256>>>(p_ln, Wh, bh, p_v, p_k);
    // minGRU scan + first residual -> g_x2
    scan_phase1<<<B_ * NC_, H_>>>(p_k, p_v, p_A, p_Bv);
    scan_phase2<<<B_, H_>>>(p_A, p_Bv, p_hin);
    scan_phase3<<<B_ * NC_, H_>>>(p_k, p_v, p_hin, x, p_x2);
    // LN2
    ln_kernel<<<BT_ / 8, 256>>>(p_x2, ln2g, ln2b, p_ln);
    // FFN
    gemm_kernel<2><<<gg, 256>>>(p_ln, W1, b1, p_h1, nullptr);
    gemm_kernel<3><<<gg, 256>>>(p_h1, W2, b2, out, p_x2);
}

// round 3
// speedup vs baseline: 1.7314x; 1.7314x over previous
#include <cuda_runtime.h>
#include <cuda_bf16.h>
#include <stdint.h>
#include <math.h>

// Problem constants: B=4, T=8192, H=512
#define B_ 4
#define T_ 8192
#define H_ 512
#define BT_ (B_ * T_)          // 32768 rows
#define CL_ 128                // scan chunk length
#define NC_ (T_ / CL_)         // 64 chunks

// ---------------------------------------------------------------------------
// Scratch (device globals; no runtime allocation allowed)
// ---------------------------------------------------------------------------
__device__ float g_ln [(size_t)BT_ * H_];   // LN output (reused for LN1 and LN2)
__device__ float g_k  [(size_t)BT_ * H_];   // raw k, then c = sigmoid(-k)
__device__ float g_v  [(size_t)BT_ * H_];   // v = z * g(preh)
__device__ float g_x2 [(size_t)BT_ * H_];   // x after first residual
__device__ float g_h1 [(size_t)BT_ * H_];   // FFN hidden
__device__ float g_A  [B_ * H_ * NC_];      // per-chunk coeff product
__device__ float g_Bv [B_ * H_ * NC_];      // per-chunk affine term
__device__ float g_hin[B_ * H_ * NC_];      // per-chunk entry state

// ---------------------------------------------------------------------------
// helpers
// ---------------------------------------------------------------------------
__device__ __forceinline__ float gfun(float x) {
    // g(x) = x + 0.5 for x >= 0 else sigmoid(x)
    return x >= 0.f ? x + 0.5f : 1.f / (1.f + expf(-x));
}

__device__ __forceinline__ unsigned int smem_u32(const void* p) {
    return (unsigned int)__cvta_generic_to_shared(p);
}

__device__ __forceinline__ void ldsm_x4(unsigned int (&r)[4], unsigned int addr) {
    asm volatile("ldmatrix.sync.aligned.m8n8.x4.shared.b16 {%0,%1,%2,%3}, [%4];"
                 : "=r"(r[0]), "=r"(r[1]), "=r"(r[2]), "=r"(r[3]) : "r"(addr));
}
__device__ __forceinline__ void ldsm_x4t(unsigned int (&r)[4], unsigned int addr) {
    asm volatile("ldmatrix.sync.aligned.m8n8.x4.trans.shared.b16 {%0,%1,%2,%3}, [%4];"
                 : "=r"(r[0]), "=r"(r[1]), "=r"(r[2]), "=r"(r[3]) : "r"(addr));
}
__device__ __forceinline__ void mma_bf16(float (&d)[4], const unsigned int (&a)[4],
                                         const unsigned int* b) {
    asm volatile(
        "mma.sync.aligned.m16n8k16.row.col.f32.bf16.bf16.f32 "
        "{%0,%1,%2,%3}, {%4,%5,%6,%7}, {%8,%9}, {%0,%1,%2,%3};"
        : "+f"(d[0]), "+f"(d[1]), "+f"(d[2]), "+f"(d[3])
        : "r"(a[0]), "r"(a[1]), "r"(a[2]), "r"(a[3]), "r"(b[0]), "r"(b[1]));
}

__device__ __forceinline__ void split_bf16(float x, __nv_bfloat16& hi, __nv_bfloat16& lo) {
    hi = __float2bfloat16(x);
    lo = __float2bfloat16(x - __bfloat162float(hi));
}

// ---------------------------------------------------------------------------
// LayerNorm: one warp per row (H=512 -> 4 float4 per lane)
// ---------------------------------------------------------------------------
__global__ __launch_bounds__(256) void ln_kernel(
    const float* __restrict__ in, const float* __restrict__ gam,
    const float* __restrict__ bet, float* __restrict__ out)
{
    const int lane = threadIdx.x & 31;
    const int row  = blockIdx.x * 8 + (threadIdx.x >> 5);
    const float4* p = (const float4*)(in + (size_t)row * H_);
    float4* q = (float4*)(out + (size_t)row * H_);

    float4 v[4];
    float s = 0.f, ss = 0.f;
#pragma unroll
    for (int i = 0; i < 4; ++i) {
        v[i] = p[lane + 32 * i];
        s  += v[i].x + v[i].y + v[i].z + v[i].w;
        ss += v[i].x * v[i].x + v[i].y * v[i].y + v[i].z * v[i].z + v[i].w * v[i].w;
    }
#pragma unroll
    for (int o = 16; o; o >>= 1) {
        s  += __shfl_xor_sync(0xffffffffu, s,  o);
        ss += __shfl_xor_sync(0xffffffffu, ss, o);
    }
    const float mu  = s * (1.f / H_);
    const float var = ss * (1.f / H_) - mu * mu;
    const float r   = rsqrtf(var + 1e-5f);
#pragma unroll
    for (int i = 0; i < 4; ++i) {
        const int c4 = lane + 32 * i;
        float4 g4 = ((const float4*)gam)[c4];
        float4 b4 = ((const float4*)bet)[c4];
        float4 o4;
        o4.x = (v[i].x - mu) * r * g4.x + b4.x;
        o4.y = (v[i].y - mu) * r * g4.y + b4.y;
        o4.z = (v[i].z - mu) * r * g4.z + b4.z;
        o4.w = (v[i].w - mu) * r * g4.w + b4.w;
        q[c4] = o4;
    }
}

// ---------------------------------------------------------------------------
// Tensor-core GEMM (bf16x3 split, fp32 accumulate)
//   out[M=32768, N=512] = A[M,512] @ W[512,512] (+ epilogue)
// CTA tile 128(M) x 64(N), 8 warps (4x2), warp tile 32x32 = 2x4 m16n8 atoms.
// K loop: 32 chunks of k16, double-buffered smem.
// EPI: 0 = acc+bias -> out
//      1 = gate: aux holds raw k; write c=sigmoid(-k) to aux, v=z*g(acc+b) to out
//      2 = relu(acc+bias) -> out
//      3 = acc+bias+aux -> out (residual)
// ---------------------------------------------------------------------------
#define ASTRIDE 24   // halfs per A smem row (16 + pad 8)
#define BSTRIDE 72   // halfs per B smem row (64 + pad 8)

template<int EPI>
__global__ __launch_bounds__(256, 2) void gemm_tc(
    const float* __restrict__ A, const float* __restrict__ W,
    const float* __restrict__ bias, float* __restrict__ out,
    float* __restrict__ aux)
{
    __shared__ __align__(16) __nv_bfloat16 As[2][2][128 * ASTRIDE];
    __shared__ __align__(16) __nv_bfloat16 Bs[2][2][16 * BSTRIDE];

    const int tid  = threadIdx.x;
    const int lane = tid & 31;
    const int warp = tid >> 5;
    const int wm   = (warp >> 1) * 32;   // warp M offset in tile
    const int wn   = (warp & 1) * 32;    // warp N offset in tile
    const int m0   = blockIdx.y * 128;
    const int n0   = blockIdx.x * 64;

    // gmem load assignments
    const int arow  = tid >> 1;
    const int akoff = (tid & 1) * 8;
    const float* Ag = A + (size_t)(m0 + arow) * 512 + akoff;
    const int bk = tid >> 4;
    const int bn = (tid & 15) * 4;
    const float* Bg = W + (size_t)bk * 512 + n0 + bn;

    float acc[2][4][4];
#pragma unroll
    for (int i = 0; i < 2; ++i)
#pragma unroll
        for (int j = 0; j < 4; ++j)
#pragma unroll
            for (int l = 0; l < 4; ++l) acc[i][j][l] = 0.f;

    // ldmatrix lane addressing (constant offsets within a tile)
    const int a_row_sel = lane & 15;          // m within 16-row atom
    const int a_k_sel   = (lane >> 4) * 8;    // k half
    const int b_k_sel   = lane & 15;          // k row
    const int b_n_sel   = (lane >> 4) * 8;    // n half within 16

    // prologue: load chunk 0 into buf 0
    {
        float4 a0 = *(const float4*)(Ag);
        float4 a1 = *(const float4*)(Ag + 4);
        float4 b0 = *(const float4*)(Bg);
        const float av[8] = {a0.x, a0.y, a0.z, a0.w, a1.x, a1.y, a1.z, a1.w};
#pragma unroll
        for (int j = 0; j < 8; ++j) {
            __nv_bfloat16 h, l; split_bf16(av[j], h, l);
            As[0][0][arow * ASTRIDE + akoff + j] = h;
            As[0][1][arow * ASTRIDE + akoff + j] = l;
        }
        const float bv[4] = {b0.x, b0.y, b0.z, b0.w};
#pragma unroll
        for (int j = 0; j < 4; ++j) {
            __nv_bfloat16 h, l; split_bf16(bv[j], h, l);
            Bs[0][0][bk * BSTRIDE + bn + j] = h;
            Bs[0][1][bk * BSTRIDE + bn + j] = l;
        }
    }
    __syncthreads();

    for (int kc = 0; kc < 32; ++kc) {
        const int cur = kc & 1;

        // prefetch next chunk into registers
        float av[8], bv[4];
        if (kc < 31) {
            float4 a0 = *(const float4*)(Ag + (kc + 1) * 16);
            float4 a1 = *(const float4*)(Ag + (kc + 1) * 16 + 4);
            float4 b0 = *(const float4*)(Bg + (size_t)(kc + 1) * 16 * 512);
            av[0]=a0.x; av[1]=a0.y; av[2]=a0.z; av[3]=a0.w;
            av[4]=a1.x; av[5]=a1.y; av[6]=a1.z; av[7]=a1.w;
            bv[0]=b0.x; bv[1]=b0.y; bv[2]=b0.z; bv[3]=b0.w;
        }

        // fragment loads
        unsigned int ah[2][4], al[2][4];
#pragma unroll
        for (int mi = 0; mi < 2; ++mi) {
            unsigned int addr_h = smem_u32(&As[cur][0][(wm + mi * 16 + a_row_sel) * ASTRIDE + a_k_sel]);
            unsigned int addr_l = smem_u32(&As[cur][1][(wm + mi * 16 + a_row_sel) * ASTRIDE + a_k_sel]);
            ldsm_x4(ah[mi], addr_h);
            ldsm_x4(al[mi], addr_l);
        }
        unsigned int bh[2][4], bl[2][4];
#pragma unroll
        for (int nb = 0; nb < 2; ++nb) {
            unsigned int addr_h = smem_u32(&Bs[cur][0][b_k_sel * BSTRIDE + wn + nb * 16 + b_n_sel]);
            unsigned int addr_l = smem_u32(&Bs[cur][1][b_k_sel * BSTRIDE + wn + nb * 16 + b_n_sel]);
            ldsm_x4t(bh[nb], addr_h);
            ldsm_x4t(bl[nb], addr_l);
        }

        // 24 MMAs: (Ah,Bh), (Ah,Bl), (Al,Bh)
#pragma unroll
        for (int mi = 0; mi < 2; ++mi)
#pragma unroll
            for (int nb = 0; nb < 2; ++nb) {
                mma_bf16(acc[mi][2 * nb + 0], ah[mi], &bh[nb][0]);
                mma_bf16(acc[mi][2 * nb + 1], ah[mi], &bh[nb][2]);
                mma_bf16(acc[mi][2 * nb + 0], ah[mi], &bl[nb][0]);
                mma_bf16(acc[mi][2 * nb + 1], ah[mi], &bl[nb][2]);
                mma_bf16(acc[mi][2 * nb + 0], al[mi], &bh[nb][0]);
                mma_bf16(acc[mi][2 * nb + 1], al[mi], &bh[nb][2]);
            }

        // stage next chunk
        if (kc < 31) {
            const int nxt = cur ^ 1;
#pragma unroll
            for (int j = 0; j < 8; ++j) {
                __nv_bfloat16 h, l; split_bf16(av[j], h, l);
                As[nxt][0][arow * ASTRIDE + akoff + j] = h;
                As[nxt][1][arow * ASTRIDE + akoff + j] = l;
            }
#pragma unroll
            for (int j = 0; j < 4; ++j) {
                __nv_bfloat16 h, l; split_bf16(bv[j], h, l);
                Bs[nxt][0][bk * BSTRIDE + bn + j] = h;
                Bs[nxt][1][bk * BSTRIDE + bn + j] = l;
            }
        }
        __syncthreads();
    }

    // epilogue
    const int group = lane >> 2;
    const int tig2  = (lane & 3) * 2;
#pragma unroll
    for (int mi = 0; mi < 2; ++mi) {
#pragma unroll
        for (int ni = 0; ni < 4; ++ni) {
            const int col = n0 + wn + ni * 8 + tig2;
            const float bx = bias[col], by = bias[col + 1];
#pragma unroll
            for (int half = 0; half < 2; ++half) {
                const int row = m0 + wm + mi * 16 + group + half * 8;
                const size_t o = (size_t)row * 512 + col;
                float rx = acc[mi][ni][half * 2 + 0] + bx;
                float ry = acc[mi][ni][half * 2 + 1] + by;
                if (EPI == 0) {
                    *(float2*)(out + o) = make_float2(rx, ry);
                } else if (EPI == 1) {
                    float2 k2 = *(const float2*)(aux + o);
                    float cx = 1.f / (1.f + expf(k2.x));
                    float cy = 1.f / (1.f + expf(k2.y));
                    float vx = (1.f - cx) * gfun(rx);
                    float vy = (1.f - cy) * gfun(ry);
                    *(float2*)(aux + o) = make_float2(cx, cy);
                    *(float2*)(out + o) = make_float2(vx, vy);
                } else if (EPI == 2) {
                    *(float2*)(out + o) = make_float2(fmaxf(rx, 0.f), fmaxf(ry, 0.f));
                } else {
                    float2 x2 = *(const float2*)(aux + o);
                    *(float2*)(out + o) = make_float2(rx + x2.x, ry + x2.y);
                }
            }
        }
    }
}

// ---------------------------------------------------------------------------
// Chunked scan: h_t = c_t * h_{t-1} + v_t, h_0 = 0.5, over T per (b,h) channel.
// ---------------------------------------------------------------------------
__global__ __launch_bounds__(512) void scan_phase1(
    const float* __restrict__ c, const float* __restrict__ v,
    float* __restrict__ Aout, float* __restrict__ Bout)
{
    const int h  = threadIdx.x;
    const int bj = blockIdx.x;                 // b*NC + j
    const int b  = bj >> 6, j = bj & (NC_ - 1);
    size_t base = ((size_t)b * T_ + (size_t)j * CL_) * H_ + h;
    float A = 1.f, Bv = 0.f;
    for (int t = 0; t < CL_; ++t) {
        const float ct = c[base];
        const float vt = v[base];
        Bv = fmaf(ct, Bv, vt);
        A *= ct;
        base += H_;
    }
    Aout[bj * H_ + h] = A;
    Bout[bj * H_ + h] = Bv;
}

__global__ __launch_bounds__(512) void scan_phase2(
    const float* __restrict__ A, const float* __restrict__ Bv,
    float* __restrict__ hin)
{
    const int h = threadIdx.x;
    const int b = blockIdx.x;
    float hr = 0.5f;
#pragma unroll
    for (int j = 0; j < NC_; ++j) {
        const int idx = (b * NC_ + j) * H_ + h;
        hin[idx] = hr;
        hr = fmaf(A[idx], hr, Bv[idx]);
    }
}

__global__ __launch_bounds__(512) void scan_phase3(
    const float* __restrict__ c, const float* __restrict__ v,
    const float* __restrict__ hin, const float* __restrict__ x,
    float* __restrict__ x2)
{
    const int h  = threadIdx.x;
    const int bj = blockIdx.x;
    const int b  = bj >> 6, j = bj & (NC_ - 1);
    size_t base = ((size_t)b * T_ + (size_t)j * CL_) * H_ + h;
    float hr = hin[bj * H_ + h];
    for (int t = 0; t < CL_; ++t) {
        hr = fmaf(c[base], hr, v[base]);
        x2[base] = x[base] + hr;
        base += H_;
    }
}

// ---------------------------------------------------------------------------
// launch
// ---------------------------------------------------------------------------
extern "C" void kernel_launch(void* const* d_in, const int* in_sizes, int n_in,
                              void* d_out, int out_size)
{
    const float* x    = (const float*)d_in[0];
    const float* ln1g = (const float*)d_in[1];
    const float* ln1b = (const float*)d_in[2];
    const float* Wz   = (const float*)d_in[3];
    const float* bz   = (const float*)d_in[4];
    const float* Wh   = (const float*)d_in[5];
    const float* bh   = (const float*)d_in[6];
    const float* ln2g = (const float*)d_in[7];
    const float* ln2b = (const float*)d_in[8];
    const float* W1   = (const float*)d_in[9];
    const float* b1   = (const float*)d_in[10];
    const float* W2   = (const float*)d_in[11];
    const float* b2   = (const float*)d_in[12];
    float* out = (float*)d_out;

    float *p_ln, *p_k, *p_v, *p_x2, *p_h1, *p_A, *p_Bv, *p_hin;
    cudaGetSymbolAddress((void**)&p_ln,  g_ln);
    cudaGetSymbolAddress((void**)&p_k,   g_k);
    cudaGetSymbolAddress((void**)&p_v,   g_v);
    cudaGetSymbolAddress((void**)&p_x2,  g_x2);
    cudaGetSymbolAddress((void**)&p_h1,  g_h1);
    cudaGetSymbolAddress((void**)&p_A,   g_A);
    cudaGetSymbolAddress((void**)&p_Bv,  g_Bv);
    cudaGetSymbolAddress((void**)&p_hin, g_hin);

    const dim3 gg(512 / 64, BT_ / 128);   // (8, 256)

    // x_ln = LN1(x)
    ln_kernel<<<BT_ / 8, 256>>>(x, ln1g, ln1b, p_ln);
    // k = x_ln @ Wz + bz (raw)
    gemm_tc<0><<<gg, 256>>>(p_ln, Wz, bz, p_k, nullptr);
    // preh = x_ln @ Wh + bh ; c = sigmoid(-k) -> g_k ; v = sigmoid(k)*g(preh) -> g_v
    gemm_tc<1><<<gg, 256>>>(p_ln, Wh, bh, p_v, p_k);
    // minGRU scan + first residual -> g_x2
    scan_phase1<<<B_ * NC_, H_>>>(p_k, p_v, p_A, p_Bv);
    scan_phase2<<<B_, H_>>>(p_A, p_Bv, p_hin);
    scan_phase3<<<B_ * NC_, H_>>>(p_k, p_v, p_hin, x, p_x2);
    // LN2
    ln_kernel<<<BT_ / 8, 256>>>(p_x2, ln2g, ln2b, p_ln);
    // FFN
    gemm_tc<2><<<gg, 256>>>(p_ln, W1, b1, p_h1, nullptr);
    gemm_tc<3><<<gg, 256>>>(p_h1, W2, b2, out, p_x2);
}

// round 5
// speedup vs baseline: 1.8646x; 1.0769x over previous
#include <cuda_runtime.h>
#include <cuda_bf16.h>
#include <stdint.h>
#include <math.h>

// Problem constants: B=4, T=8192, H=512
#define B_ 4
#define T_ 8192
#define H_ 512
#define BT_ (B_ * T_)          // 32768 rows
#define CL_ 128                // scan chunk length
#define NC_ (T_ / CL_)         // 64 chunks

// ---------------------------------------------------------------------------
// Scratch (device globals)
// ---------------------------------------------------------------------------
__device__ float g_k  [(size_t)BT_ * H_];   // raw k, then c = sigmoid(-k)
__device__ float g_v  [(size_t)BT_ * H_];   // v = z * g(preh)
__device__ float g_x2 [(size_t)BT_ * H_];   // x after first residual
__device__ __nv_bfloat16 g_ah [(size_t)BT_ * H_];  // activation hi split
__device__ __nv_bfloat16 g_al [(size_t)BT_ * H_];  // activation lo split
__device__ __nv_bfloat16 g_h1h[(size_t)BT_ * H_];  // FFN hidden hi
__device__ __nv_bfloat16 g_h1l[(size_t)BT_ * H_];  // FFN hidden lo
// weight splits, original [K,N] row-major layout
__device__ __nv_bfloat16 g_wzh[H_ * H_], g_wzl[H_ * H_];
__device__ __nv_bfloat16 g_whh[H_ * H_], g_whl[H_ * H_];
__device__ __nv_bfloat16 g_w1h[H_ * H_], g_w1l[H_ * H_];
__device__ __nv_bfloat16 g_w2h[H_ * H_], g_w2l[H_ * H_];
__device__ float g_A  [B_ * H_ * NC_];
__device__ float g_Bv [B_ * H_ * NC_];
__device__ float g_hin[B_ * H_ * NC_];

// ---------------------------------------------------------------------------
// helpers
// ---------------------------------------------------------------------------
__device__ __forceinline__ float gfun(float x) {
    return x >= 0.f ? x + 0.5f : 1.f / (1.f + expf(-x));
}
__device__ __forceinline__ void split_bf16(float x, __nv_bfloat16& hi, __nv_bfloat16& lo) {
    hi = __float2bfloat16(x);
    lo = __float2bfloat16(x - __bfloat162float(hi));
}
__device__ __forceinline__ unsigned int smem_u32(const void* p) {
    return (unsigned int)__cvta_generic_to_shared(p);
}
__device__ __forceinline__ void ldsm_x4(unsigned int (&r)[4], unsigned int addr) {
    asm volatile("ldmatrix.sync.aligned.m8n8.x4.shared.b16 {%0,%1,%2,%3}, [%4];"
                 : "=r"(r[0]), "=r"(r[1]), "=r"(r[2]), "=r"(r[3]) : "r"(addr));
}
__device__ __forceinline__ void ldsm_x4t(unsigned int (&r)[4], unsigned int addr) {
    asm volatile("ldmatrix.sync.aligned.m8n8.x4.trans.shared.b16 {%0,%1,%2,%3}, [%4];"
                 : "=r"(r[0]), "=r"(r[1]), "=r"(r[2]), "=r"(r[3]) : "r"(addr));
}
__device__ __forceinline__ void mma_bf16(float (&d)[4], const unsigned int (&a)[4],
                                         const unsigned int* b) {
    asm volatile(
        "mma.sync.aligned.m16n8k16.row.col.f32.bf16.bf16.f32 "
        "{%0,%1,%2,%3}, {%4,%5,%6,%7}, {%8,%9}, {%0,%1,%2,%3};"
        : "+f"(d[0]), "+f"(d[1]), "+f"(d[2]), "+f"(d[3])
        : "r"(a[0]), "r"(a[1]), "r"(a[2]), "r"(a[3]), "r"(b[0]), "r"(b[1]));
}
__device__ __forceinline__ void cp16(unsigned int dst, const void* src) {
    asm volatile("cp.async.cg.shared.global [%0], [%1], 16;" :: "r"(dst), "l"(src));
}
__device__ __forceinline__ void cp_commit() {
    asm volatile("cp.async.commit_group;" ::: "memory");
}
template<int N>
__device__ __forceinline__ void cp_wait() {
    asm volatile("cp.async.wait_group %0;" :: "n"(N) : "memory");
}

// ---------------------------------------------------------------------------
// LayerNorm + bf16 hi/lo split: one warp per row
// ---------------------------------------------------------------------------
__global__ __launch_bounds__(256) void ln_split_kernel(
    const float* __restrict__ in, const float* __restrict__ gam,
    const float* __restrict__ bet, __nv_bfloat16* __restrict__ oh,
    __nv_bfloat16* __restrict__ ol)
{
    const int lane = threadIdx.x & 31;
    const int row  = blockIdx.x * 8 + (threadIdx.x >> 5);
    const float4* p = (const float4*)(in + (size_t)row * H_);

    float4 v[4];
    float s = 0.f, ss = 0.f;
#pragma unroll
    for (int i = 0; i < 4; ++i) {
        v[i] = p[lane + 32 * i];
        s  += v[i].x + v[i].y + v[i].z + v[i].w;
        ss += v[i].x * v[i].x + v[i].y * v[i].y + v[i].z * v[i].z + v[i].w * v[i].w;
    }
#pragma unroll
    for (int o = 16; o; o >>= 1) {
        s  += __shfl_xor_sync(0xffffffffu, s,  o);
        ss += __shfl_xor_sync(0xffffffffu, ss, o);
    }
    const float mu  = s * (1.f / H_);
    const float var = ss * (1.f / H_) - mu * mu;
    const float r   = rsqrtf(var + 1e-5f);
#pragma unroll
    for (int i = 0; i < 4; ++i) {
        const int c4 = lane + 32 * i;
        float4 g4 = ((const float4*)gam)[c4];
        float4 b4 = ((const float4*)bet)[c4];
        float o0 = (v[i].x - mu) * r * g4.x + b4.x;
        float o1 = (v[i].y - mu) * r * g4.y + b4.y;
        float o2 = (v[i].z - mu) * r * g4.z + b4.z;
        float o3 = (v[i].w - mu) * r * g4.w + b4.w;
        __nv_bfloat16 h0,h1,h2,h3,l0,l1,l2,l3;
        split_bf16(o0,h0,l0); split_bf16(o1,h1,l1);
        split_bf16(o2,h2,l2); split_bf16(o3,h3,l3);
        const size_t off = (size_t)row * H_ + c4 * 4;
        *(__nv_bfloat162*)(oh + off)     = __nv_bfloat162(h0, h1);
        *(__nv_bfloat162*)(oh + off + 2) = __nv_bfloat162(h2, h3);
        *(__nv_bfloat162*)(ol + off)     = __nv_bfloat162(l0, l1);
        *(__nv_bfloat162*)(ol + off + 2) = __nv_bfloat162(l2, l3);
    }
}

// ---------------------------------------------------------------------------
// Weight elementwise split (keeps [K,N] layout)
// ---------------------------------------------------------------------------
__global__ __launch_bounds__(256) void wsplit_kernel(
    const float* __restrict__ W, __nv_bfloat16* __restrict__ Th,
    __nv_bfloat16* __restrict__ Tl)
{
    const int i = (blockIdx.x * 256 + threadIdx.x) * 4;
    float4 w = *(const float4*)(W + i);
    __nv_bfloat16 h0,h1,h2,h3,l0,l1,l2,l3;
    split_bf16(w.x,h0,l0); split_bf16(w.y,h1,l1);
    split_bf16(w.z,h2,l2); split_bf16(w.w,h3,l3);
    *(__nv_bfloat162*)(Th + i)     = __nv_bfloat162(h0, h1);
    *(__nv_bfloat162*)(Th + i + 2) = __nv_bfloat162(h2, h3);
    *(__nv_bfloat162*)(Tl + i)     = __nv_bfloat162(l0, l1);
    *(__nv_bfloat162*)(Tl + i + 2) = __nv_bfloat162(l2, l3);
}

// ---------------------------------------------------------------------------
// Tensor-core GEMM (bf16x3 split, fp32 accumulate, pre-split inputs)
//   out[32768, 512] = A @ W (+ epilogue)
// CTA 128(M) x 128(N), 8 warps (4x2), warp tile 32x64.
// K: 16 iterations of k32, 3-stage cp.async pipeline, 1 sync per iteration.
// smem (dynamic, bytes):
//   A hi/lo: 128 rows x 40 halves (32 k + 8 pad) = 10240 per split-stage
//   B hi/lo: 32 rows  x 136 halves (128 n + 8 pad) = 8704 per split-stage
// EPI: 0 raw->out; 1 gate; 2 relu->bf16 split; 3 residual
// ---------------------------------------------------------------------------
#define SA_SZ 10240
#define SB_SZ 8704
#define SB_BASE (3 * 2 * SA_SZ)              // 61440
#define SM_TOT  (SB_BASE + 3 * 2 * SB_SZ)    // 113664

__device__ __forceinline__ void stage_cp(
    unsigned int smb, int slot, int kidx, int tid, int m0, int n0,
    const __nv_bfloat16* __restrict__ Ah, const __nv_bfloat16* __restrict__ Al,
    const __nv_bfloat16* __restrict__ Bh, const __nv_bfloat16* __restrict__ Bl)
{
    const int ko = kidx * 32;
    const unsigned int abase = smb + slot * 2 * SA_SZ;
    const unsigned int bbase = smb + SB_BASE + slot * 2 * SB_SZ;
#pragma unroll
    for (int i = 0; i < 2; ++i) {
        const int seg = tid + i * 256;          // 0..511
        const int row = seg >> 2, part = seg & 3;
        const unsigned int so = abase + row * 80 + part * 16;
        const size_t go = (size_t)(m0 + row) * H_ + ko + part * 8;
        cp16(so, Ah + go);
        cp16(so + SA_SZ, Al + go);
    }
#pragma unroll
    for (int i = 0; i < 2; ++i) {
        const int seg = tid + i * 256;          // 0..511
        const int row = seg >> 4, part = seg & 15;
        const unsigned int so = bbase + row * 272 + part * 16;
        const size_t go = (size_t)(ko + row) * H_ + n0 + part * 8;
        cp16(so, Bh + go);
        cp16(so + SB_SZ, Bl + go);
    }
}

template<int EPI>
__global__ __launch_bounds__(256, 1) void gemm_tc(
    const __nv_bfloat16* __restrict__ Ah, const __nv_bfloat16* __restrict__ Al,
    const __nv_bfloat16* __restrict__ Bh, const __nv_bfloat16* __restrict__ Bl,
    const float* __restrict__ bias, float* __restrict__ out,
    float* __restrict__ aux, __nv_bfloat16* __restrict__ outh,
    __nv_bfloat16* __restrict__ outl)
{
    extern __shared__ char smem[];
    const unsigned int smb = smem_u32(smem);
    const int tid  = threadIdx.x;
    const int lane = tid & 31;
    const int warp = tid >> 5;
    const int wm   = (warp >> 1) * 32;
    const int wn   = (warp & 1) * 64;
    const int m0   = blockIdx.y * 128;
    const int n0   = blockIdx.x * 128;

    float acc[2][8][4];
#pragma unroll
    for (int i = 0; i < 2; ++i)
#pragma unroll
        for (int j = 0; j < 8; ++j)
#pragma unroll
            for (int l = 0; l < 4; ++l) acc[i][j][l] = 0.f;

    const int a_row_sel = lane & 15;
    const int a_k_sel   = (lane >> 4) * 8;
    const int b_k_sel   = lane & 15;
    const int b_n_sel   = (lane >> 4) * 8;

    stage_cp(smb, 0, 0, tid, m0, n0, Ah, Al, Bh, Bl); cp_commit();
    stage_cp(smb, 1, 1, tid, m0, n0, Ah, Al, Bh, Bl); cp_commit();

#pragma unroll 1
    for (int it = 0; it < 16; ++it) {
        cp_wait<1>();
        __syncthreads();
        if (it + 2 < 16) {
            stage_cp(smb, (it + 2) % 3, it + 2, tid, m0, n0, Ah, Al, Bh, Bl);
            cp_commit();
        }
        const int slot = it % 3;
        const unsigned int abase = smb + slot * 2 * SA_SZ;
        const unsigned int bbase = smb + SB_BASE + slot * 2 * SB_SZ;
#pragma unroll
        for (int ks = 0; ks < 2; ++ks) {
            unsigned int ah[2][4], al[2][4];
#pragma unroll
            for (int mi = 0; mi < 2; ++mi) {
                const unsigned int ad = abase +
                    ((wm + mi * 16 + a_row_sel) * 40 + ks * 16 + a_k_sel) * 2;
                ldsm_x4(ah[mi], ad);
                ldsm_x4(al[mi], ad + SA_SZ);
            }
            unsigned int bh[4][4], bl[4][4];
#pragma unroll
            for (int nb = 0; nb < 4; ++nb) {
                const unsigned int bd = bbase +
                    ((ks * 16 + b_k_sel) * 136 + wn + nb * 16 + b_n_sel) * 2;
                ldsm_x4t(bh[nb], bd);
                ldsm_x4t(bl[nb], bd + SB_SZ);
            }
#pragma unroll
            for (int mi = 0; mi < 2; ++mi)
#pragma unroll
                for (int nb = 0; nb < 4; ++nb) {
                    mma_bf16(acc[mi][2 * nb + 0], ah[mi], &bh[nb][0]);
                    mma_bf16(acc[mi][2 * nb + 1], ah[mi], &bh[nb][2]);
                    mma_bf16(acc[mi][2 * nb + 0], ah[mi], &bl[nb][0]);
                    mma_bf16(acc[mi][2 * nb + 1], ah[mi], &bl[nb][2]);
                    mma_bf16(acc[mi][2 * nb + 0], al[mi], &bh[nb][0]);
                    mma_bf16(acc[mi][2 * nb + 1], al[mi], &bh[nb][2]);
                }
        }
    }

    // epilogue
    const int group = lane >> 2;
    const int tig2  = (lane & 3) * 2;
#pragma unroll
    for (int mi = 0; mi < 2; ++mi) {
#pragma unroll
        for (int ni = 0; ni < 8; ++ni) {
            const int col = n0 + wn + ni * 8 + tig2;
            const float bx = bias[col], by = bias[col + 1];
#pragma unroll
            for (int half = 0; half < 2; ++half) {
                const int row = m0 + wm + mi * 16 + group + half * 8;
                const size_t o = (size_t)row * H_ + col;
                float rx = acc[mi][ni][half * 2 + 0] + bx;
                float ry = acc[mi][ni][half * 2 + 1] + by;
                if (EPI == 0) {
                    *(float2*)(out + o) = make_float2(rx, ry);
                } else if (EPI == 1) {
                    float2 k2 = *(const float2*)(aux + o);
                    float cx = 1.f / (1.f + expf(k2.x));
                    float cy = 1.f / (1.f + expf(k2.y));
                    float vx = (1.f - cx) * gfun(rx);
                    float vy = (1.f - cy) * gfun(ry);
                    *(float2*)(aux + o) = make_float2(cx, cy);
                    *(float2*)(out + o) = make_float2(vx, vy);
                } else if (EPI == 2) {
                    rx = fmaxf(rx, 0.f); ry = fmaxf(ry, 0.f);
                    __nv_bfloat16 h0,h1,l0,l1;
                    split_bf16(rx, h0, l0); split_bf16(ry, h1, l1);
                    *(__nv_bfloat162*)(outh + o) = __nv_bfloat162(h0, h1);
                    *(__nv_bfloat162*)(outl + o) = __nv_bfloat162(l0, l1);
                } else {
                    float2 x2 = *(const float2*)(aux + o);
                    *(float2*)(out + o) = make_float2(rx + x2.x, ry + x2.y);
                }
            }
        }
    }
}

// ---------------------------------------------------------------------------
// Chunked scan (unchanged, near its HBM roofline)
// ---------------------------------------------------------------------------
__global__ __launch_bounds__(512) void scan_phase1(
    const float* __restrict__ c, const float* __restrict__ v,
    float* __restrict__ Aout, float* __restrict__ Bout)
{
    const int h  = threadIdx.x;
    const int bj = blockIdx.x;
    const int b  = bj >> 6, j = bj & (NC_ - 1);
    size_t base = ((size_t)b * T_ + (size_t)j * CL_) * H_ + h;
    float A = 1.f, Bv = 0.f;
    for (int t = 0; t < CL_; ++t) {
        const float ct = c[base];
        const float vt = v[base];
        Bv = fmaf(ct, Bv, vt);
        A *= ct;
        base += H_;
    }
    Aout[bj * H_ + h] = A;
    Bout[bj * H_ + h] = Bv;
}

__global__ __launch_bounds__(512) void scan_phase2(
    const float* __restrict__ A, const float* __restrict__ Bv,
    float* __restrict__ hin)
{
    const int h = threadIdx.x;
    const int b = blockIdx.x;
    float hr = 0.5f;
#pragma unroll
    for (int j = 0; j < NC_; ++j) {
        const int idx = (b * NC_ + j) * H_ + h;
        hin[idx] = hr;
        hr = fmaf(A[idx], hr, Bv[idx]);
    }
}

__global__ __launch_bounds__(512) void scan_phase3(
    const float* __restrict__ c, const float* __restrict__ v,
    const float* __restrict__ hin, const float* __restrict__ x,
    float* __restrict__ x2)
{
    const int h  = threadIdx.x;
    const int bj = blockIdx.x;
    const int b  = bj >> 6, j = bj & (NC_ - 1);
    size_t base = ((size_t)b * T_ + (size_t)j * CL_) * H_ + h;
    float hr = hin[bj * H_ + h];
    for (int t = 0; t < CL_; ++t) {
        hr = fmaf(c[base], hr, v[base]);
        x2[base] = x[base] + hr;
        base += H_;
    }
}

// ---------------------------------------------------------------------------
// launch
// ---------------------------------------------------------------------------
extern "C" void kernel_launch(void* const* d_in, const int* in_sizes, int n_in,
                              void* d_out, int out_size)
{
    const float* x    = (const float*)d_in[0];
    const float* ln1g = (const float*)d_in[1];
    const float* ln1b = (const float*)d_in[2];
    const float* Wz   = (const float*)d_in[3];
    const float* bz   = (const float*)d_in[4];
    const float* Wh   = (const float*)d_in[5];
    const float* bh   = (const float*)d_in[6];
    const float* ln2g = (const float*)d_in[7];
    const float* ln2b = (const float*)d_in[8];
    const float* W1   = (const float*)d_in[9];
    const float* b1   = (const float*)d_in[10];
    const float* W2   = (const float*)d_in[11];
    const float* b2   = (const float*)d_in[12];
    float* out = (float*)d_out;

    float *p_k, *p_v, *p_x2, *p_A, *p_Bv, *p_hin;
    __nv_bfloat16 *p_ah, *p_al, *p_h1h, *p_h1l;
    __nv_bfloat16 *p_wzh, *p_wzl, *p_whh, *p_whl, *p_w1h, *p_w1l, *p_w2h, *p_w2l;
    cudaGetSymbolAddress((void**)&p_k,   g_k);
    cudaGetSymbolAddress((void**)&p_v,   g_v);
    cudaGetSymbolAddress((void**)&p_x2,  g_x2);
    cudaGetSymbolAddress((void**)&p_ah,  g_ah);
    cudaGetSymbolAddress((void**)&p_al,  g_al);
    cudaGetSymbolAddress((void**)&p_h1h, g_h1h);
    cudaGetSymbolAddress((void**)&p_h1l, g_h1l);
    cudaGetSymbolAddress((void**)&p_wzh, g_wzh);
    cudaGetSymbolAddress((void**)&p_wzl, g_wzl);
    cudaGetSymbolAddress((void**)&p_whh, g_whh);
    cudaGetSymbolAddress((void**)&p_whl, g_whl);
    cudaGetSymbolAddress((void**)&p_w1h, g_w1h);
    cudaGetSymbolAddress((void**)&p_w1l, g_w1l);
    cudaGetSymbolAddress((void**)&p_w2h, g_w2h);
    cudaGetSymbolAddress((void**)&p_w2l, g_w2l);
    cudaGetSymbolAddress((void**)&p_A,   g_A);
    cudaGetSymbolAddress((void**)&p_Bv,  g_Bv);
    cudaGetSymbolAddress((void**)&p_hin, g_hin);

    cudaFuncSetAttribute(gemm_tc<0>, cudaFuncAttributeMaxDynamicSharedMemorySize, SM_TOT);
    cudaFuncSetAttribute(gemm_tc<1>, cudaFuncAttributeMaxDynamicSharedMemorySize, SM_TOT);
    cudaFuncSetAttribute(gemm_tc<2>, cudaFuncAttributeMaxDynamicSharedMemorySize, SM_TOT);
    cudaFuncSetAttribute(gemm_tc<3>, cudaFuncAttributeMaxDynamicSharedMemorySize, SM_TOT);

    const dim3 ggrid(4, BT_ / 128);    // (N tiles, M tiles) = (4, 256)

    // one-shot weight splits
    wsplit_kernel<<<H_ * H_ / 1024, 256>>>(Wz, p_wzh, p_wzl);
    wsplit_kernel<<<H_ * H_ / 1024, 256>>>(Wh, p_whh, p_whl);
    wsplit_kernel<<<H_ * H_ / 1024, 256>>>(W1, p_w1h, p_w1l);
    wsplit_kernel<<<H_ * H_ / 1024, 256>>>(W2, p_w2h, p_w2l);

    // LN1 -> split activations
    ln_split_kernel<<<BT_ / 8, 256>>>(x, ln1g, ln1b, p_ah, p_al);
    // k raw
    gemm_tc<0><<<ggrid, 256, SM_TOT>>>(p_ah, p_al, p_wzh, p_wzl, bz, p_k, nullptr, nullptr, nullptr);
    // preh -> c (g_k), v (g_v)
    gemm_tc<1><<<ggrid, 256, SM_TOT>>>(p_ah, p_al, p_whh, p_whl, bh, p_v, p_k, nullptr, nullptr);
    // scan + residual -> g_x2
    scan_phase1<<<B_ * NC_, H_>>>(p_k, p_v, p_A, p_Bv);
    scan_phase2<<<B_, H_>>>(p_A, p_Bv, p_hin);
    scan_phase3<<<B_ * NC_, H_>>>(p_k, p_v, p_hin, x, p_x2);
    // LN2 -> split activations
    ln_split_kernel<<<BT_ / 8, 256>>>(p_x2, ln2g, ln2b, p_ah, p_al);
    // FFN
    gemm_tc<2><<<ggrid, 256, SM_TOT>>>(p_ah, p_al, p_w1h, p_w1l, b1, nullptr, nullptr, p_h1h, p_h1l);
    gemm_tc<3><<<ggrid, 256, SM_TOT>>>(p_h1h, p_h1l, p_w2h, p_w2l, b2, out, p_x2, nullptr, nullptr);
}

// round 6
// speedup vs baseline: 1.8667x; 1.0011x over previous
#include <cuda_runtime.h>
#include <cuda_bf16.h>
#include <stdint.h>
#include <math.h>

// Problem constants: B=4, T=8192, H=512
#define B_ 4
#define T_ 8192
#define H_ 512
#define BT_ (B_ * T_)          // 32768 rows
#define CL_ 128                // scan chunk length
#define NC_ (T_ / CL_)         // 64 chunks

// ---------------------------------------------------------------------------
// Scratch (device globals)
// ---------------------------------------------------------------------------
__device__ float g_k  [(size_t)BT_ * H_];   // raw k, then c = sigmoid(-k)
__device__ float g_v  [(size_t)BT_ * H_];   // v = z * g(preh)
__device__ float g_x2 [(size_t)BT_ * H_];   // x after first residual
__device__ __nv_bfloat16 g_ah [(size_t)BT_ * H_];  // activation hi split
__device__ __nv_bfloat16 g_al [(size_t)BT_ * H_];  // activation lo split
__device__ __nv_bfloat16 g_h1h[(size_t)BT_ * H_];  // FFN hidden hi
__device__ __nv_bfloat16 g_h1l[(size_t)BT_ * H_];  // FFN hidden lo
// weight splits, original [K,N] row-major layout
__device__ __nv_bfloat16 g_wzh[H_ * H_], g_wzl[H_ * H_];
__device__ __nv_bfloat16 g_whh[H_ * H_], g_whl[H_ * H_];
__device__ __nv_bfloat16 g_w1h[H_ * H_], g_w1l[H_ * H_];
__device__ __nv_bfloat16 g_w2h[H_ * H_], g_w2l[H_ * H_];
__device__ float g_A  [B_ * H_ * NC_];
__device__ float g_Bv [B_ * H_ * NC_];
__device__ float g_hin[B_ * H_ * NC_];

// ---------------------------------------------------------------------------
// helpers
// ---------------------------------------------------------------------------
__device__ __forceinline__ float gfun(float x) {
    return x >= 0.f ? x + 0.5f : 1.f / (1.f + expf(-x));
}
__device__ __forceinline__ void split_bf16(float x, __nv_bfloat16& hi, __nv_bfloat16& lo) {
    hi = __float2bfloat16(x);
    lo = __float2bfloat16(x - __bfloat162float(hi));
}
__device__ __forceinline__ unsigned int smem_u32(const void* p) {
    return (unsigned int)__cvta_generic_to_shared(p);
}
__device__ __forceinline__ void ldsm_x4(unsigned int (&r)[4], unsigned int addr) {
    asm volatile("ldmatrix.sync.aligned.m8n8.x4.shared.b16 {%0,%1,%2,%3}, [%4];"
                 : "=r"(r[0]), "=r"(r[1]), "=r"(r[2]), "=r"(r[3]) : "r"(addr));
}
__device__ __forceinline__ void ldsm_x4t(unsigned int (&r)[4], unsigned int addr) {
    asm volatile("ldmatrix.sync.aligned.m8n8.x4.trans.shared.b16 {%0,%1,%2,%3}, [%4];"
                 : "=r"(r[0]), "=r"(r[1]), "=r"(r[2]), "=r"(r[3]) : "r"(addr));
}
__device__ __forceinline__ void mma_bf16(float (&d)[4], const unsigned int (&a)[4],
                                         const unsigned int* b) {
    asm volatile(
        "mma.sync.aligned.m16n8k16.row.col.f32.bf16.bf16.f32 "
        "{%0,%1,%2,%3}, {%4,%5,%6,%7}, {%8,%9}, {%0,%1,%2,%3};"
        : "+f"(d[0]), "+f"(d[1]), "+f"(d[2]), "+f"(d[3])
        : "r"(a[0]), "r"(a[1]), "r"(a[2]), "r"(a[3]), "r"(b[0]), "r"(b[1]));
}
__device__ __forceinline__ void cp16(unsigned int dst, const void* src) {
    asm volatile("cp.async.cg.shared.global [%0], [%1], 16;" :: "r"(dst), "l"(src));
}
__device__ __forceinline__ void cp_commit() {
    asm volatile("cp.async.commit_group;" ::: "memory");
}
template<int N>
__device__ __forceinline__ void cp_wait() {
    asm volatile("cp.async.wait_group %0;" :: "n"(N) : "memory");
}

// ---------------------------------------------------------------------------
// LayerNorm + bf16 hi/lo split: one warp per row
// ---------------------------------------------------------------------------
__global__ __launch_bounds__(256) void ln_split_kernel(
    const float* __restrict__ in, const float* __restrict__ gam,
    const float* __restrict__ bet, __nv_bfloat16* __restrict__ oh,
    __nv_bfloat16* __restrict__ ol)
{
    const int lane = threadIdx.x & 31;
    const int row  = blockIdx.x * 8 + (threadIdx.x >> 5);
    const float4* p = (const float4*)(in + (size_t)row * H_);

    float4 v[4];
    float s = 0.f, ss = 0.f;
#pragma unroll
    for (int i = 0; i < 4; ++i) {
        v[i] = p[lane + 32 * i];
        s  += v[i].x + v[i].y + v[i].z + v[i].w;
        ss += v[i].x * v[i].x + v[i].y * v[i].y + v[i].z * v[i].z + v[i].w * v[i].w;
    }
#pragma unroll
    for (int o = 16; o; o >>= 1) {
        s  += __shfl_xor_sync(0xffffffffu, s,  o);
        ss += __shfl_xor_sync(0xffffffffu, ss, o);
    }
    const float mu  = s * (1.f / H_);
    const float var = ss * (1.f / H_) - mu * mu;
    const float r   = rsqrtf(var + 1e-5f);
#pragma unroll
    for (int i = 0; i < 4; ++i) {
        const int c4 = lane + 32 * i;
        float4 g4 = ((const float4*)gam)[c4];
        float4 b4 = ((const float4*)bet)[c4];
        float o0 = (v[i].x - mu) * r * g4.x + b4.x;
        float o1 = (v[i].y - mu) * r * g4.y + b4.y;
        float o2 = (v[i].z - mu) * r * g4.z + b4.z;
        float o3 = (v[i].w - mu) * r * g4.w + b4.w;
        __nv_bfloat16 h0,h1,h2,h3,l0,l1,l2,l3;
        split_bf16(o0,h0,l0); split_bf16(o1,h1,l1);
        split_bf16(o2,h2,l2); split_bf16(o3,h3,l3);
        const size_t off = (size_t)row * H_ + c4 * 4;
        *(__nv_bfloat162*)(oh + off)     = __nv_bfloat162(h0, h1);
        *(__nv_bfloat162*)(oh + off + 2) = __nv_bfloat162(h2, h3);
        *(__nv_bfloat162*)(ol + off)     = __nv_bfloat162(l0, l1);
        *(__nv_bfloat162*)(ol + off + 2) = __nv_bfloat162(l2, l3);
    }
}

// ---------------------------------------------------------------------------
// Weight elementwise split (keeps [K,N] layout)
// ---------------------------------------------------------------------------
__global__ __launch_bounds__(256) void wsplit_kernel(
    const float* __restrict__ W, __nv_bfloat16* __restrict__ Th,
    __nv_bfloat16* __restrict__ Tl)
{
    const int i = (blockIdx.x * 256 + threadIdx.x) * 4;
    float4 w = *(const float4*)(W + i);
    __nv_bfloat16 h0,h1,h2,h3,l0,l1,l2,l3;
    split_bf16(w.x,h0,l0); split_bf16(w.y,h1,l1);
    split_bf16(w.z,h2,l2); split_bf16(w.w,h3,l3);
    *(__nv_bfloat162*)(Th + i)     = __nv_bfloat162(h0, h1);
    *(__nv_bfloat162*)(Th + i + 2) = __nv_bfloat162(h2, h3);
    *(__nv_bfloat162*)(Tl + i)     = __nv_bfloat162(l0, l1);
    *(__nv_bfloat162*)(Tl + i + 2) = __nv_bfloat162(l2, l3);
}

// ---------------------------------------------------------------------------
// Tensor-core GEMM (bf16x3 split, fp32 accumulate, pre-split inputs)
//   out[32768, 512] = A @ W (+ epilogue)
// CTA 128(M) x 128(N), 8 warps (4x2), warp tile 32x64.
// K: 16 iterations of k32, 3-stage cp.async pipeline, 1 sync per iteration.
// MMAs issued TERM-MAJOR: 16x AhBh, then 16x AhBl, then 16x AlBh, so each
// accumulator is reused at distance 16 (RAW latency fully hidden).
// EPI: 0 raw->out; 1 gate; 2 relu->bf16 split; 3 residual
// ---------------------------------------------------------------------------
#define SA_SZ 10240
#define SB_SZ 8704
#define SB_BASE (3 * 2 * SA_SZ)              // 61440
#define SM_TOT  (SB_BASE + 3 * 2 * SB_SZ)    // 113664

__device__ __forceinline__ void stage_cp(
    unsigned int smb, int slot, int kidx, int tid, int m0, int n0,
    const __nv_bfloat16* __restrict__ Ah, const __nv_bfloat16* __restrict__ Al,
    const __nv_bfloat16* __restrict__ Bh, const __nv_bfloat16* __restrict__ Bl)
{
    const int ko = kidx * 32;
    const unsigned int abase = smb + slot * 2 * SA_SZ;
    const unsigned int bbase = smb + SB_BASE + slot * 2 * SB_SZ;
#pragma unroll
    for (int i = 0; i < 2; ++i) {
        const int seg = tid + i * 256;          // 0..511
        const int row = seg >> 2, part = seg & 3;
        const unsigned int so = abase + row * 80 + part * 16;
        const size_t go = (size_t)(m0 + row) * H_ + ko + part * 8;
        cp16(so, Ah + go);
        cp16(so + SA_SZ, Al + go);
    }
#pragma unroll
    for (int i = 0; i < 2; ++i) {
        const int seg = tid + i * 256;          // 0..511
        const int row = seg >> 4, part = seg & 15;
        const unsigned int so = bbase + row * 272 + part * 16;
        const size_t go = (size_t)(ko + row) * H_ + n0 + part * 8;
        cp16(so, Bh + go);
        cp16(so + SB_SZ, Bl + go);
    }
}

template<int EPI>
__global__ __launch_bounds__(256, 1) void gemm_tc(
    const __nv_bfloat16* __restrict__ Ah, const __nv_bfloat16* __restrict__ Al,
    const __nv_bfloat16* __restrict__ Bh, const __nv_bfloat16* __restrict__ Bl,
    const float* __restrict__ bias, float* __restrict__ out,
    float* __restrict__ aux, __nv_bfloat16* __restrict__ outh,
    __nv_bfloat16* __restrict__ outl)
{
    extern __shared__ char smem[];
    const unsigned int smb = smem_u32(smem);
    const int tid  = threadIdx.x;
    const int lane = tid & 31;
    const int warp = tid >> 5;
    const int wm   = (warp >> 1) * 32;
    const int wn   = (warp & 1) * 64;
    const int m0   = blockIdx.y * 128;
    const int n0   = blockIdx.x * 128;

    float acc[2][8][4];
#pragma unroll
    for (int i = 0; i < 2; ++i)
#pragma unroll
        for (int j = 0; j < 8; ++j)
#pragma unroll
            for (int l = 0; l < 4; ++l) acc[i][j][l] = 0.f;

    const int a_row_sel = lane & 15;
    const int a_k_sel   = (lane >> 4) * 8;
    const int b_k_sel   = lane & 15;
    const int b_n_sel   = (lane >> 4) * 8;

    stage_cp(smb, 0, 0, tid, m0, n0, Ah, Al, Bh, Bl); cp_commit();
    stage_cp(smb, 1, 1, tid, m0, n0, Ah, Al, Bh, Bl); cp_commit();

#pragma unroll 1
    for (int it = 0; it < 16; ++it) {
        cp_wait<1>();
        __syncthreads();
        if (it + 2 < 16) {
            stage_cp(smb, (it + 2) % 3, it + 2, tid, m0, n0, Ah, Al, Bh, Bl);
            cp_commit();
        }
        const int slot = it % 3;
        const unsigned int abase = smb + slot * 2 * SA_SZ;
        const unsigned int bbase = smb + SB_BASE + slot * 2 * SB_SZ;
#pragma unroll
        for (int ks = 0; ks < 2; ++ks) {
            unsigned int ah[2][4], al[2][4];
#pragma unroll
            for (int mi = 0; mi < 2; ++mi) {
                const unsigned int ad = abase +
                    ((wm + mi * 16 + a_row_sel) * 40 + ks * 16 + a_k_sel) * 2;
                ldsm_x4(ah[mi], ad);
                ldsm_x4(al[mi], ad + SA_SZ);
            }
            unsigned int bh[4][4], bl[4][4];
#pragma unroll
            for (int nb = 0; nb < 4; ++nb) {
                const unsigned int bd = bbase +
                    ((ks * 16 + b_k_sel) * 136 + wn + nb * 16 + b_n_sel) * 2;
                ldsm_x4t(bh[nb], bd);
                ldsm_x4t(bl[nb], bd + SB_SZ);
            }
            // term-major issue: 16 independent MMAs per term, acc reuse
            // distance = 16 so HMMA accumulate latency never binds.
#pragma unroll
            for (int mi = 0; mi < 2; ++mi)
#pragma unroll
                for (int nb = 0; nb < 4; ++nb) {
                    mma_bf16(acc[mi][2 * nb + 0], ah[mi], &bh[nb][0]);
                    mma_bf16(acc[mi][2 * nb + 1], ah[mi], &bh[nb][2]);
                }
#pragma unroll
            for (int mi = 0; mi < 2; ++mi)
#pragma unroll
                for (int nb = 0; nb < 4; ++nb) {
                    mma_bf16(acc[mi][2 * nb + 0], ah[mi], &bl[nb][0]);
                    mma_bf16(acc[mi][2 * nb + 1], ah[mi], &bl[nb][2]);
                }
#pragma unroll
            for (int mi = 0; mi < 2; ++mi)
#pragma unroll
                for (int nb = 0; nb < 4; ++nb) {
                    mma_bf16(acc[mi][2 * nb + 0], al[mi], &bh[nb][0]);
                    mma_bf16(acc[mi][2 * nb + 1], al[mi], &bh[nb][2]);
                }
        }
    }

    // epilogue
    const int group = lane >> 2;
    const int tig2  = (lane & 3) * 2;
#pragma unroll
    for (int mi = 0; mi < 2; ++mi) {
#pragma unroll
        for (int ni = 0; ni < 8; ++ni) {
            const int col = n0 + wn + ni * 8 + tig2;
            const float bx = bias[col], by = bias[col + 1];
#pragma unroll
            for (int half = 0; half < 2; ++half) {
                const int row = m0 + wm + mi * 16 + group + half * 8;
                const size_t o = (size_t)row * H_ + col;
                float rx = acc[mi][ni][half * 2 + 0] + bx;
                float ry = acc[mi][ni][half * 2 + 1] + by;
                if (EPI == 0) {
                    *(float2*)(out + o) = make_float2(rx, ry);
                } else if (EPI == 1) {
                    float2 k2 = *(const float2*)(aux + o);
                    float cx = 1.f / (1.f + expf(k2.x));
                    float cy = 1.f / (1.f + expf(k2.y));
                    float vx = (1.f - cx) * gfun(rx);
                    float vy = (1.f - cy) * gfun(ry);
                    *(float2*)(aux + o) = make_float2(cx, cy);
                    *(float2*)(out + o) = make_float2(vx, vy);
                } else if (EPI == 2) {
                    rx = fmaxf(rx, 0.f); ry = fmaxf(ry, 0.f);
                    __nv_bfloat16 h0,h1,l0,l1;
                    split_bf16(rx, h0, l0); split_bf16(ry, h1, l1);
                    *(__nv_bfloat162*)(outh + o) = __nv_bfloat162(h0, h1);
                    *(__nv_bfloat162*)(outl + o) = __nv_bfloat162(l0, l1);
                } else {
                    float2 x2 = *(const float2*)(aux + o);
                    *(float2*)(out + o) = make_float2(rx + x2.x, ry + x2.y);
                }
            }
        }
    }
}

// ---------------------------------------------------------------------------
// Chunked scan (unchanged, near its HBM roofline)
// ---------------------------------------------------------------------------
__global__ __launch_bounds__(512) void scan_phase1(
    const float* __restrict__ c, const float* __restrict__ v,
    float* __restrict__ Aout, float* __restrict__ Bout)
{
    const int h  = threadIdx.x;
    const int bj = blockIdx.x;
    const int b  = bj >> 6, j = bj & (NC_ - 1);
    size_t base = ((size_t)b * T_ + (size_t)j * CL_) * H_ + h;
    float A = 1.f, Bv = 0.f;
    for (int t = 0; t < CL_; ++t) {
        const float ct = c[base];
        const float vt = v[base];
        Bv = fmaf(ct, Bv, vt);
        A *= ct;
        base += H_;
    }
    Aout[bj * H_ + h] = A;
    Bout[bj * H_ + h] = Bv;
}

__global__ __launch_bounds__(512) void scan_phase2(
    const float* __restrict__ A, const float* __restrict__ Bv,
    float* __restrict__ hin)
{
    const int h = threadIdx.x;
    const int b = blockIdx.x;
    float hr = 0.5f;
#pragma unroll
    for (int j = 0; j < NC_; ++j) {
        const int idx = (b * NC_ + j) * H_ + h;
        hin[idx] = hr;
        hr = fmaf(A[idx], hr, Bv[idx]);
    }
}

__global__ __launch_bounds__(512) void scan_phase3(
    const float* __restrict__ c, const float* __restrict__ v,
    const float* __restrict__ hin, const float* __restrict__ x,
    float* __restrict__ x2)
{
    const int h  = threadIdx.x;
    const int bj = blockIdx.x;
    const int b  = bj >> 6, j = bj & (NC_ - 1);
    size_t base = ((size_t)b * T_ + (size_t)j * CL_) * H_ + h;
    float hr = hin[bj * H_ + h];
    for (int t = 0; t < CL_; ++t) {
        hr = fmaf(c[base], hr, v[base]);
        x2[base] = x[base] + hr;
        base += H_;
    }
}

// ---------------------------------------------------------------------------
// launch
// ---------------------------------------------------------------------------
extern "C" void kernel_launch(void* const* d_in, const int* in_sizes, int n_in,
                              void* d_out, int out_size)
{
    const float* x    = (const float*)d_in[0];
    const float* ln1g = (const float*)d_in[1];
    const float* ln1b = (const float*)d_in[2];
    const float* Wz   = (const float*)d_in[3];
    const float* bz   = (const float*)d_in[4];
    const float* Wh   = (const float*)d_in[5];
    const float* bh   = (const float*)d_in[6];
    const float* ln2g = (const float*)d_in[7];
    const float* ln2b = (const float*)d_in[8];
    const float* W1   = (const float*)d_in[9];
    const float* b1   = (const float*)d_in[10];
    const float* W2   = (const float*)d_in[11];
    const float* b2   = (const float*)d_in[12];
    float* out = (float*)d_out;

    float *p_k, *p_v, *p_x2, *p_A, *p_Bv, *p_hin;
    __nv_bfloat16 *p_ah, *p_al, *p_h1h, *p_h1l;
    __nv_bfloat16 *p_wzh, *p_wzl, *p_whh, *p_whl, *p_w1h, *p_w1l, *p_w2h, *p_w2l;
    cudaGetSymbolAddress((void**)&p_k,   g_k);
    cudaGetSymbolAddress((void**)&p_v,   g_v);
    cudaGetSymbolAddress((void**)&p_x2,  g_x2);
    cudaGetSymbolAddress((void**)&p_ah,  g_ah);
    cudaGetSymbolAddress((void**)&p_al,  g_al);
    cudaGetSymbolAddress((void**)&p_h1h, g_h1h);
    cudaGetSymbolAddress((void**)&p_h1l, g_h1l);
    cudaGetSymbolAddress((void**)&p_wzh, g_wzh);
    cudaGetSymbolAddress((void**)&p_wzl, g_wzl);
    cudaGetSymbolAddress((void**)&p_whh, g_whh);
    cudaGetSymbolAddress((void**)&p_whl, g_whl);
    cudaGetSymbolAddress((void**)&p_w1h, g_w1h);
    cudaGetSymbolAddress((void**)&p_w1l, g_w1l);
    cudaGetSymbolAddress((void**)&p_w2h, g_w2h);
    cudaGetSymbolAddress((void**)&p_w2l, g_w2l);
    cudaGetSymbolAddress((void**)&p_A,   g_A);
    cudaGetSymbolAddress((void**)&p_Bv,  g_Bv);
    cudaGetSymbolAddress((void**)&p_hin, g_hin);

    cudaFuncSetAttribute(gemm_tc<0>, cudaFuncAttributeMaxDynamicSharedMemorySize, SM_TOT);
    cudaFuncSetAttribute(gemm_tc<1>, cudaFuncAttributeMaxDynamicSharedMemorySize, SM_TOT);
    cudaFuncSetAttribute(gemm_tc<2>, cudaFuncAttributeMaxDynamicSharedMemorySize, SM_TOT);
    cudaFuncSetAttribute(gemm_tc<3>, cudaFuncAttributeMaxDynamicSharedMemorySize, SM_TOT);

    const dim3 ggrid(4, BT_ / 128);    // (N tiles, M tiles) = (4, 256)

    // one-shot weight splits
    wsplit_kernel<<<H_ * H_ / 1024, 256>>>(Wz, p_wzh, p_wzl);
    wsplit_kernel<<<H_ * H_ / 1024, 256>>>(Wh, p_whh, p_whl);
    wsplit_kernel<<<H_ * H_ / 1024, 256>>>(W1, p_w1h, p_w1l);
    wsplit_kernel<<<H_ * H_ / 1024, 256>>>(W2, p_w2h, p_w2l);

    // LN1 -> split activations
    ln_split_kernel<<<BT_ / 8, 256>>>(x, ln1g, ln1b, p_ah, p_al);
    // k raw
    gemm_tc<0><<<ggrid, 256, SM_TOT>>>(p_ah, p_al, p_wzh, p_wzl, bz, p_k, nullptr, nullptr, nullptr);
    // preh -> c (g_k), v (g_v)
    gemm_tc<1><<<ggrid, 256, SM_TOT>>>(p_ah, p_al, p_whh, p_whl, bh, p_v, p_k, nullptr, nullptr);
    // scan + residual -> g_x2
    scan_phase1<<<B_ * NC_, H_>>>(p_k, p_v, p_A, p_Bv);
    scan_phase2<<<B_, H_>>>(p_A, p_Bv, p_hin);
    scan_phase3<<<B_ * NC_, H_>>>(p_k, p_v, p_hin, x, p_x2);
    // LN2 -> split activations
    ln_split_kernel<<<BT_ / 8, 256>>>(p_x2, ln2g, ln2b, p_ah, p_al);
    // FFN
    gemm_tc<2><<<ggrid, 256, SM_TOT>>>(p_ah, p_al, p_w1h, p_w1l, b1, nullptr, nullptr, p_h1h, p_h1l);
    gemm_tc<3><<<ggrid, 256, SM_TOT>>>(p_h1h, p_h1l, p_w2h, p_w2l, b2, out, p_x2, nullptr, nullptr);
}

// round 7
// speedup vs baseline: 2.2534x; 1.2072x over previous
#include <cuda_runtime.h>
#include <cuda_fp16.h>
#include <stdint.h>
#include <math.h>

// Problem constants: B=4, T=8192, H=512
#define B_ 4
#define T_ 8192
#define H_ 512
#define BT_ (B_ * T_)          // 32768 rows
#define CL_ 128                // scan chunk length
#define NC_ (T_ / CL_)         // 64 chunks

// ---------------------------------------------------------------------------
// Scratch (device globals)
// ---------------------------------------------------------------------------
__device__ float g_k  [(size_t)BT_ * H_];   // raw k, then c = sigmoid(-k)
__device__ float g_v  [(size_t)BT_ * H_];   // v = z * g(preh)
__device__ float g_x2 [(size_t)BT_ * H_];   // x after first residual
__device__ __half g_ah [(size_t)BT_ * H_];  // activation hi split (fp16)
__device__ __half g_al [(size_t)BT_ * H_];  // activation lo split (fp16)
__device__ __half g_h1h[(size_t)BT_ * H_];  // FFN hidden hi
__device__ __half g_h1l[(size_t)BT_ * H_];  // FFN hidden lo
// single-fp16 weights, original [K,N] row-major layout
__device__ __half g_wz[H_ * H_];
__device__ __half g_wh[H_ * H_];
__device__ __half g_w1[H_ * H_];
__device__ __half g_w2[H_ * H_];
__device__ float g_A  [B_ * H_ * NC_];
__device__ float g_Bv [B_ * H_ * NC_];
__device__ float g_hin[B_ * H_ * NC_];

// ---------------------------------------------------------------------------
// helpers
// ---------------------------------------------------------------------------
__device__ __forceinline__ float gfun(float x) {
    return x >= 0.f ? x + 0.5f : 1.f / (1.f + expf(-x));
}
__device__ __forceinline__ void split_fp16(float x, __half& hi, __half& lo) {
    hi = __float2half_rn(x);
    lo = __float2half_rn(x - __half2float(hi));
}
__device__ __forceinline__ unsigned int smem_u32(const void* p) {
    return (unsigned int)__cvta_generic_to_shared(p);
}
__device__ __forceinline__ void ldsm_x4(unsigned int (&r)[4], unsigned int addr) {
    asm volatile("ldmatrix.sync.aligned.m8n8.x4.shared.b16 {%0,%1,%2,%3}, [%4];"
                 : "=r"(r[0]), "=r"(r[1]), "=r"(r[2]), "=r"(r[3]) : "r"(addr));
}
__device__ __forceinline__ void ldsm_x4t(unsigned int (&r)[4], unsigned int addr) {
    asm volatile("ldmatrix.sync.aligned.m8n8.x4.trans.shared.b16 {%0,%1,%2,%3}, [%4];"
                 : "=r"(r[0]), "=r"(r[1]), "=r"(r[2]), "=r"(r[3]) : "r"(addr));
}
__device__ __forceinline__ void mma_f16(float (&d)[4], const unsigned int (&a)[4],
                                        const unsigned int* b) {
    asm volatile(
        "mma.sync.aligned.m16n8k16.row.col.f32.f16.f16.f32 "
        "{%0,%1,%2,%3}, {%4,%5,%6,%7}, {%8,%9}, {%0,%1,%2,%3};"
        : "+f"(d[0]), "+f"(d[1]), "+f"(d[2]), "+f"(d[3])
        : "r"(a[0]), "r"(a[1]), "r"(a[2]), "r"(a[3]), "r"(b[0]), "r"(b[1]));
}
__device__ __forceinline__ void cp16(unsigned int dst, const void* src) {
    asm volatile("cp.async.cg.shared.global [%0], [%1], 16;" :: "r"(dst), "l"(src));
}
__device__ __forceinline__ void cp_commit() {
    asm volatile("cp.async.commit_group;" ::: "memory");
}
template<int N>
__device__ __forceinline__ void cp_wait() {
    asm volatile("cp.async.wait_group %0;" :: "n"(N) : "memory");
}

// ---------------------------------------------------------------------------
// LayerNorm + fp16 hi/lo split: one warp per row
// ---------------------------------------------------------------------------
__global__ __launch_bounds__(256) void ln_split_kernel(
    const float* __restrict__ in, const float* __restrict__ gam,
    const float* __restrict__ bet, __half* __restrict__ oh,
    __half* __restrict__ ol)
{
    const int lane = threadIdx.x & 31;
    const int row  = blockIdx.x * 8 + (threadIdx.x >> 5);
    const float4* p = (const float4*)(in + (size_t)row * H_);

    float4 v[4];
    float s = 0.f, ss = 0.f;
#pragma unroll
    for (int i = 0; i < 4; ++i) {
        v[i] = p[lane + 32 * i];
        s  += v[i].x + v[i].y + v[i].z + v[i].w;
        ss += v[i].x * v[i].x + v[i].y * v[i].y + v[i].z * v[i].z + v[i].w * v[i].w;
    }
#pragma unroll
    for (int o = 16; o; o >>= 1) {
        s  += __shfl_xor_sync(0xffffffffu, s,  o);
        ss += __shfl_xor_sync(0xffffffffu, ss, o);
    }
    const float mu  = s * (1.f / H_);
    const float var = ss * (1.f / H_) - mu * mu;
    const float r   = rsqrtf(var + 1e-5f);
#pragma unroll
    for (int i = 0; i < 4; ++i) {
        const int c4 = lane + 32 * i;
        float4 g4 = ((const float4*)gam)[c4];
        float4 b4 = ((const float4*)bet)[c4];
        float o0 = (v[i].x - mu) * r * g4.x + b4.x;
        float o1 = (v[i].y - mu) * r * g4.y + b4.y;
        float o2 = (v[i].z - mu) * r * g4.z + b4.z;
        float o3 = (v[i].w - mu) * r * g4.w + b4.w;
        __half h0,h1,h2,h3,l0,l1,l2,l3;
        split_fp16(o0,h0,l0); split_fp16(o1,h1,l1);
        split_fp16(o2,h2,l2); split_fp16(o3,h3,l3);
        const size_t off = (size_t)row * H_ + c4 * 4;
        *(__half2*)(oh + off)     = __halves2half2(h0, h1);
        *(__half2*)(oh + off + 2) = __halves2half2(h2, h3);
        *(__half2*)(ol + off)     = __halves2half2(l0, l1);
        *(__half2*)(ol + off + 2) = __halves2half2(l2, l3);
    }
}

// ---------------------------------------------------------------------------
// Batched weight fp16 convert: 4 weights in one launch (keeps [K,N] layout)
// ---------------------------------------------------------------------------
__global__ __launch_bounds__(256) void wconv_kernel(
    const float* __restrict__ W0, const float* __restrict__ W1,
    const float* __restrict__ W2, const float* __restrict__ W3,
    __half* __restrict__ O0, __half* __restrict__ O1,
    __half* __restrict__ O2, __half* __restrict__ O3)
{
    const int which = blockIdx.x >> 8;
    const int blk   = blockIdx.x & 255;
    const float* W = which == 0 ? W0 : which == 1 ? W1 : which == 2 ? W2 : W3;
    __half* O      = which == 0 ? O0 : which == 1 ? O1 : which == 2 ? O2 : O3;
    const int i = (blk * 256 + threadIdx.x) * 4;
    float4 w = *(const float4*)(W + i);
    *(__half2*)(O + i)     = __halves2half2(__float2half_rn(w.x), __float2half_rn(w.y));
    *(__half2*)(O + i + 2) = __halves2half2(__float2half_rn(w.z), __float2half_rn(w.w));
}

// ---------------------------------------------------------------------------
// Tensor-core GEMM (fp16 2-term split: D = Ah*B + Al*B, fp32 accumulate)
//   out[32768, 512] = A @ W (+ epilogue)
// CTA 128(M) x 128(N), 8 warps (4x2), warp tile 32x64.
// K: 16 iterations of k32, 3-stage cp.async pipeline, 1 sync per iteration.
// EPI: 0 raw->out; 1 gate; 2 relu->fp16 split; 3 residual
// ---------------------------------------------------------------------------
#define SA_SZ 10240                           // 128 rows x 80B (64B data + 16 pad)
#define SB_SZ 8704                            // 32 rows x 272B (256B data + 16 pad)
#define SB_BASE (3 * 2 * SA_SZ)               // 61440
#define SM_TOT  (SB_BASE + 3 * SB_SZ)         // 87552

__device__ __forceinline__ void stage_cp(
    unsigned int smb, int slot, int kidx, int tid, int m0, int n0,
    const __half* __restrict__ Ah, const __half* __restrict__ Al,
    const __half* __restrict__ Bh)
{
    const int ko = kidx * 32;
    const unsigned int abase = smb + slot * 2 * SA_SZ;
    const unsigned int bbase = smb + SB_BASE + slot * SB_SZ;
#pragma unroll
    for (int i = 0; i < 2; ++i) {
        const int seg = tid + i * 256;          // 0..511
        const int row = seg >> 2, part = seg & 3;
        const unsigned int so = abase + row * 80 + part * 16;
        const size_t go = (size_t)(m0 + row) * H_ + ko + part * 8;
        cp16(so, Ah + go);
        cp16(so + SA_SZ, Al + go);
    }
#pragma unroll
    for (int i = 0; i < 2; ++i) {
        const int seg = tid + i * 256;          // 0..511
        const int row = seg >> 4, part = seg & 15;
        const unsigned int so = bbase + row * 272 + part * 16;
        const size_t go = (size_t)(ko + row) * H_ + n0 + part * 8;
        cp16(so, Bh + go);
    }
}

template<int EPI>
__global__ __launch_bounds__(256, 1) void gemm_tc(
    const __half* __restrict__ Ah, const __half* __restrict__ Al,
    const __half* __restrict__ Bh,
    const float* __restrict__ bias, float* __restrict__ out,
    float* __restrict__ aux, __half* __restrict__ outh,
    __half* __restrict__ outl)
{
    extern __shared__ char smem[];
    const unsigned int smb = smem_u32(smem);
    const int tid  = threadIdx.x;
    const int lane = tid & 31;
    const int warp = tid >> 5;
    const int wm   = (warp >> 1) * 32;
    const int wn   = (warp & 1) * 64;
    const int m0   = blockIdx.y * 128;
    const int n0   = blockIdx.x * 128;

    float acc[2][8][4];
#pragma unroll
    for (int i = 0; i < 2; ++i)
#pragma unroll
        for (int j = 0; j < 8; ++j)
#pragma unroll
            for (int l = 0; l < 4; ++l) acc[i][j][l] = 0.f;

    const int a_row_sel = lane & 15;
    const int a_k_sel   = (lane >> 4) * 8;
    const int b_k_sel   = lane & 15;
    const int b_n_sel   = (lane >> 4) * 8;

    stage_cp(smb, 0, 0, tid, m0, n0, Ah, Al, Bh); cp_commit();
    stage_cp(smb, 1, 1, tid, m0, n0, Ah, Al, Bh); cp_commit();

#pragma unroll 1
    for (int it = 0; it < 16; ++it) {
        cp_wait<1>();
        __syncthreads();
        if (it + 2 < 16) {
            stage_cp(smb, (it + 2) % 3, it + 2, tid, m0, n0, Ah, Al, Bh);
            cp_commit();
        }
        const int slot = it % 3;
        const unsigned int abase = smb + slot * 2 * SA_SZ;
        const unsigned int bbase = smb + SB_BASE + slot * SB_SZ;
#pragma unroll
        for (int ks = 0; ks < 2; ++ks) {
            unsigned int ah[2][4], al[2][4];
#pragma unroll
            for (int mi = 0; mi < 2; ++mi) {
                const unsigned int ad = abase +
                    ((wm + mi * 16 + a_row_sel) * 40 + ks * 16 + a_k_sel) * 2;
                ldsm_x4(ah[mi], ad);
                ldsm_x4(al[mi], ad + SA_SZ);
            }
            unsigned int bh[4][4];
#pragma unroll
            for (int nb = 0; nb < 4; ++nb) {
                const unsigned int bd = bbase +
                    ((ks * 16 + b_k_sel) * 136 + wn + nb * 16 + b_n_sel) * 2;
                ldsm_x4t(bh[nb], bd);
            }
            // term-major: 16x AhB, then 16x AlB (acc reuse distance 16)
#pragma unroll
            for (int mi = 0; mi < 2; ++mi)
#pragma unroll
                for (int nb = 0; nb < 4; ++nb) {
                    mma_f16(acc[mi][2 * nb + 0], ah[mi], &bh[nb][0]);
                    mma_f16(acc[mi][2 * nb + 1], ah[mi], &bh[nb][2]);
                }
#pragma unroll
            for (int mi = 0; mi < 2; ++mi)
#pragma unroll
                for (int nb = 0; nb < 4; ++nb) {
                    mma_f16(acc[mi][2 * nb + 0], al[mi], &bh[nb][0]);
                    mma_f16(acc[mi][2 * nb + 1], al[mi], &bh[nb][2]);
                }
        }
    }

    // epilogue
    const int group = lane >> 2;
    const int tig2  = (lane & 3) * 2;
#pragma unroll
    for (int mi = 0; mi < 2; ++mi) {
#pragma unroll
        for (int ni = 0; ni < 8; ++ni) {
            const int col = n0 + wn + ni * 8 + tig2;
            const float bx = bias[col], by = bias[col + 1];
#pragma unroll
            for (int half = 0; half < 2; ++half) {
                const int row = m0 + wm + mi * 16 + group + half * 8;
                const size_t o = (size_t)row * H_ + col;
                float rx = acc[mi][ni][half * 2 + 0] + bx;
                float ry = acc[mi][ni][half * 2 + 1] + by;
                if (EPI == 0) {
                    *(float2*)(out + o) = make_float2(rx, ry);
                } else if (EPI == 1) {
                    float2 k2 = *(const float2*)(aux + o);
                    float cx = 1.f / (1.f + expf(k2.x));
                    float cy = 1.f / (1.f + expf(k2.y));
                    float vx = (1.f - cx) * gfun(rx);
                    float vy = (1.f - cy) * gfun(ry);
                    *(float2*)(aux + o) = make_float2(cx, cy);
                    *(float2*)(out + o) = make_float2(vx, vy);
                } else if (EPI == 2) {
                    rx = fmaxf(rx, 0.f); ry = fmaxf(ry, 0.f);
                    __half h0,h1,l0,l1;
                    split_fp16(rx, h0, l0); split_fp16(ry, h1, l1);
                    *(__half2*)(outh + o) = __halves2half2(h0, h1);
                    *(__half2*)(outl + o) = __halves2half2(l0, l1);
                } else {
                    float2 x2 = *(const float2*)(aux + o);
                    *(float2*)(out + o) = make_float2(rx + x2.x, ry + x2.y);
                }
            }
        }
    }
}

// ---------------------------------------------------------------------------
// Chunked scan (unchanged, near its HBM roofline)
// ---------------------------------------------------------------------------
__global__ __launch_bounds__(512) void scan_phase1(
    const float* __restrict__ c, const float* __restrict__ v,
    float* __restrict__ Aout, float* __restrict__ Bout)
{
    const int h  = threadIdx.x;
    const int bj = blockIdx.x;
    const int b  = bj >> 6, j = bj & (NC_ - 1);
    size_t base = ((size_t)b * T_ + (size_t)j * CL_) * H_ + h;
    float A = 1.f, Bv = 0.f;
    for (int t = 0; t < CL_; ++t) {
        const float ct = c[base];
        const float vt = v[base];
        Bv = fmaf(ct, Bv, vt);
        A *= ct;
        base += H_;
    }
    Aout[bj * H_ + h] = A;
    Bout[bj * H_ + h] = Bv;
}

__global__ __launch_bounds__(512) void scan_phase2(
    const float* __restrict__ A, const float* __restrict__ Bv,
    float* __restrict__ hin)
{
    const int h = threadIdx.x;
    const int b = blockIdx.x;
    float hr = 0.5f;
#pragma unroll
    for (int j = 0; j < NC_; ++j) {
        const int idx = (b * NC_ + j) * H_ + h;
        hin[idx] = hr;
        hr = fmaf(A[idx], hr, Bv[idx]);
    }
}

__global__ __launch_bounds__(512) void scan_phase3(
    const float* __restrict__ c, const float* __restrict__ v,
    const float* __restrict__ hin, const float* __restrict__ x,
    float* __restrict__ x2)
{
    const int h  = threadIdx.x;
    const int bj = blockIdx.x;
    const int b  = bj >> 6, j = bj & (NC_ - 1);
    size_t base = ((size_t)b * T_ + (size_t)j * CL_) * H_ + h;
    float hr = hin[bj * H_ + h];
    for (int t = 0; t < CL_; ++t) {
        hr = fmaf(c[base], hr, v[base]);
        x2[base] = x[base] + hr;
        base += H_;
    }
}

// ---------------------------------------------------------------------------
// launch
// ---------------------------------------------------------------------------
extern "C" void kernel_launch(void* const* d_in, const int* in_sizes, int n_in,
                              void* d_out, int out_size)
{
    const float* x    = (const float*)d_in[0];
    const float* ln1g = (const float*)d_in[1];
    const float* ln1b = (const float*)d_in[2];
    const float* Wz   = (const float*)d_in[3];
    const float* bz   = (const float*)d_in[4];
    const float* Wh   = (const float*)d_in[5];
    const float* bh   = (const float*)d_in[6];
    const float* ln2g = (const float*)d_in[7];
    const float* ln2b = (const float*)d_in[8];
    const float* W1   = (const float*)d_in[9];
    const float* b1   = (const float*)d_in[10];
    const float* W2   = (const float*)d_in[11];
    const float* b2   = (const float*)d_in[12];
    float* out = (float*)d_out;

    float *p_k, *p_v, *p_x2, *p_A, *p_Bv, *p_hin;
    __half *p_ah, *p_al, *p_h1h, *p_h1l;
    __half *p_wz, *p_wh, *p_w1, *p_w2;
    cudaGetSymbolAddress((void**)&p_k,   g_k);
    cudaGetSymbolAddress((void**)&p_v,   g_v);
    cudaGetSymbolAddress((void**)&p_x2,  g_x2);
    cudaGetSymbolAddress((void**)&p_ah,  g_ah);
    cudaGetSymbolAddress((void**)&p_al,  g_al);
    cudaGetSymbolAddress((void**)&p_h1h, g_h1h);
    cudaGetSymbolAddress((void**)&p_h1l, g_h1l);
    cudaGetSymbolAddress((void**)&p_wz,  g_wz);
    cudaGetSymbolAddress((void**)&p_wh,  g_wh);
    cudaGetSymbolAddress((void**)&p_w1,  g_w1);
    cudaGetSymbolAddress((void**)&p_w2,  g_w2);
    cudaGetSymbolAddress((void**)&p_A,   g_A);
    cudaGetSymbolAddress((void**)&p_Bv,  g_Bv);
    cudaGetSymbolAddress((void**)&p_hin, g_hin);

    cudaFuncSetAttribute(gemm_tc<0>, cudaFuncAttributeMaxDynamicSharedMemorySize, SM_TOT);
    cudaFuncSetAttribute(gemm_tc<1>, cudaFuncAttributeMaxDynamicSharedMemorySize, SM_TOT);
    cudaFuncSetAttribute(gemm_tc<2>, cudaFuncAttributeMaxDynamicSharedMemorySize, SM_TOT);
    cudaFuncSetAttribute(gemm_tc<3>, cudaFuncAttributeMaxDynamicSharedMemorySize, SM_TOT);

    const dim3 ggrid(4, BT_ / 128);    // (N tiles, M tiles) = (4, 256)

    // one-shot batched weight convert (4 weights, one launch)
    wconv_kernel<<<1024, 256>>>(Wz, Wh, W1, W2, p_wz, p_wh, p_w1, p_w2);

    // LN1 -> split activations
    ln_split_kernel<<<BT_ / 8, 256>>>(x, ln1g, ln1b, p_ah, p_al);
    // k raw
    gemm_tc<0><<<ggrid, 256, SM_TOT>>>(p_ah, p_al, p_wz, bz, p_k, nullptr, nullptr, nullptr);
    // preh -> c (g_k), v (g_v)
    gemm_tc<1><<<ggrid, 256, SM_TOT>>>(p_ah, p_al, p_wh, bh, p_v, p_k, nullptr, nullptr);
    // scan + residual -> g_x2
    scan_phase1<<<B_ * NC_, H_>>>(p_k, p_v, p_A, p_Bv);
    scan_phase2<<<B_, H_>>>(p_A, p_Bv, p_hin);
    scan_phase3<<<B_ * NC_, H_>>>(p_k, p_v, p_hin, x, p_x2);
    // LN2 -> split activations
    ln_split_kernel<<<BT_ / 8, 256>>>(p_x2, ln2g, ln2b, p_ah, p_al);
    // FFN
    gemm_tc<2><<<ggrid, 256, SM_TOT>>>(p_ah, p_al, p_w1, b1, nullptr, nullptr, p_h1h, p_h1l);
    gemm_tc<3><<<ggrid, 256, SM_TOT>>>(p_h1h, p_h1l, p_w2, b2, out, p_x2, nullptr, nullptr);
}

// round 8
// speedup vs baseline: 2.8885x; 1.2819x over previous
#include <cuda_runtime.h>
#include <cuda_fp16.h>
#include <stdint.h>
#include <math.h>

// Problem constants: B=4, T=8192, H=512
#define B_ 4
#define T_ 8192
#define H_ 512
#define BT_ (B_ * T_)          // 32768 rows
#define CL_ 128                // scan chunk length
#define NC_ (T_ / CL_)         // 64 chunks

// ---------------------------------------------------------------------------
// Scratch (device globals)
// ---------------------------------------------------------------------------
__device__ float g_k  [(size_t)BT_ * H_];   // raw k, then c = sigmoid(-k)
__device__ float g_v  [(size_t)BT_ * H_];   // v = z * g(preh)
__device__ float g_x2 [(size_t)BT_ * H_];   // x after first residual
__device__ __half g_ah [(size_t)BT_ * H_];  // activation hi split (fp16)
__device__ __half g_al [(size_t)BT_ * H_];  // activation lo split (fp16)
__device__ __half g_h1h[(size_t)BT_ * H_];  // FFN hidden hi
__device__ __half g_h1l[(size_t)BT_ * H_];  // FFN hidden lo
// single-fp16 weights, original [K,N] row-major layout
__device__ __half g_wz[H_ * H_];
__device__ __half g_wh[H_ * H_];
__device__ __half g_w1[H_ * H_];
__device__ __half g_w2[H_ * H_];
__device__ float g_A  [B_ * H_ * NC_];
__device__ float g_Bv [B_ * H_ * NC_];
__device__ float g_hin[B_ * H_ * NC_];

// ---------------------------------------------------------------------------
// helpers
// ---------------------------------------------------------------------------
__device__ __forceinline__ float gfun(float x) {
    return x >= 0.f ? x + 0.5f : 1.f / (1.f + expf(-x));
}
__device__ __forceinline__ void split_fp16(float x, __half& hi, __half& lo) {
    hi = __float2half_rn(x);
    lo = __float2half_rn(x - __half2float(hi));
}
__device__ __forceinline__ unsigned int smem_u32(const void* p) {
    return (unsigned int)__cvta_generic_to_shared(p);
}
__device__ __forceinline__ void ldsm_x4(unsigned int (&r)[4], unsigned int addr) {
    asm volatile("ldmatrix.sync.aligned.m8n8.x4.shared.b16 {%0,%1,%2,%3}, [%4];"
                 : "=r"(r[0]), "=r"(r[1]), "=r"(r[2]), "=r"(r[3]) : "r"(addr));
}
__device__ __forceinline__ void ldsm_x4t(unsigned int (&r)[4], unsigned int addr) {
    asm volatile("ldmatrix.sync.aligned.m8n8.x4.trans.shared.b16 {%0,%1,%2,%3}, [%4];"
                 : "=r"(r[0]), "=r"(r[1]), "=r"(r[2]), "=r"(r[3]) : "r"(addr));
}
__device__ __forceinline__ void mma_f16(float (&d)[4], const unsigned int (&a)[4],
                                        const unsigned int* b) {
    asm volatile(
        "mma.sync.aligned.m16n8k16.row.col.f32.f16.f16.f32 "
        "{%0,%1,%2,%3}, {%4,%5,%6,%7}, {%8,%9}, {%0,%1,%2,%3};"
        : "+f"(d[0]), "+f"(d[1]), "+f"(d[2]), "+f"(d[3])
        : "r"(a[0]), "r"(a[1]), "r"(a[2]), "r"(a[3]), "r"(b[0]), "r"(b[1]));
}
__device__ __forceinline__ void cp16(unsigned int dst, const void* src) {
    asm volatile("cp.async.cg.shared.global [%0], [%1], 16;" :: "r"(dst), "l"(src));
}
__device__ __forceinline__ void cp_commit() {
    asm volatile("cp.async.commit_group;" ::: "memory");
}
template<int N>
__device__ __forceinline__ void cp_wait() {
    asm volatile("cp.async.wait_group %0;" :: "n"(N) : "memory");
}

// ---------------------------------------------------------------------------
// LayerNorm + fp16 hi/lo split: one warp per row
// ---------------------------------------------------------------------------
__global__ __launch_bounds__(256) void ln_split_kernel(
    const float* __restrict__ in, const float* __restrict__ gam,
    const float* __restrict__ bet, __half* __restrict__ oh,
    __half* __restrict__ ol)
{
    const int lane = threadIdx.x & 31;
    const int row  = blockIdx.x * 8 + (threadIdx.x >> 5);
    const float4* p = (const float4*)(in + (size_t)row * H_);

    float4 v[4];
    float s = 0.f, ss = 0.f;
#pragma unroll
    for (int i = 0; i < 4; ++i) {
        v[i] = p[lane + 32 * i];
        s  += v[i].x + v[i].y + v[i].z + v[i].w;
        ss += v[i].x * v[i].x + v[i].y * v[i].y + v[i].z * v[i].z + v[i].w * v[i].w;
    }
#pragma unroll
    for (int o = 16; o; o >>= 1) {
        s  += __shfl_xor_sync(0xffffffffu, s,  o);
        ss += __shfl_xor_sync(0xffffffffu, ss, o);
    }
    const float mu  = s * (1.f / H_);
    const float var = ss * (1.f / H_) - mu * mu;
    const float r   = rsqrtf(var + 1e-5f);
#pragma unroll
    for (int i = 0; i < 4; ++i) {
        const int c4 = lane + 32 * i;
        float4 g4 = ((const float4*)gam)[c4];
        float4 b4 = ((const float4*)bet)[c4];
        float o0 = (v[i].x - mu) * r * g4.x + b4.x;
        float o1 = (v[i].y - mu) * r * g4.y + b4.y;
        float o2 = (v[i].z - mu) * r * g4.z + b4.z;
        float o3 = (v[i].w - mu) * r * g4.w + b4.w;
        __half h0,h1,h2,h3,l0,l1,l2,l3;
        split_fp16(o0,h0,l0); split_fp16(o1,h1,l1);
        split_fp16(o2,h2,l2); split_fp16(o3,h3,l3);
        const size_t off = (size_t)row * H_ + c4 * 4;
        *(__half2*)(oh + off)     = __halves2half2(h0, h1);
        *(__half2*)(oh + off + 2) = __halves2half2(h2, h3);
        *(__half2*)(ol + off)     = __halves2half2(l0, l1);
        *(__half2*)(ol + off + 2) = __halves2half2(l2, l3);
    }
}

// ---------------------------------------------------------------------------
// Batched weight fp16 convert: 4 weights in one launch (keeps [K,N] layout)
// ---------------------------------------------------------------------------
__global__ __launch_bounds__(256) void wconv_kernel(
    const float* __restrict__ W0, const float* __restrict__ W1,
    const float* __restrict__ W2, const float* __restrict__ W3,
    __half* __restrict__ O0, __half* __restrict__ O1,
    __half* __restrict__ O2, __half* __restrict__ O3)
{
    const int which = blockIdx.x >> 8;
    const int blk   = blockIdx.x & 255;
    const float* W = which == 0 ? W0 : which == 1 ? W1 : which == 2 ? W2 : W3;
    __half* O      = which == 0 ? O0 : which == 1 ? O1 : which == 2 ? O2 : O3;
    const int i = (blk * 256 + threadIdx.x) * 4;
    float4 w = *(const float4*)(W + i);
    *(__half2*)(O + i)     = __halves2half2(__float2half_rn(w.x), __float2half_rn(w.y));
    *(__half2*)(O + i + 2) = __halves2half2(__float2half_rn(w.z), __float2half_rn(w.w));
}

// ---------------------------------------------------------------------------
// Tensor-core GEMM (fp16 2-term split: D = Ah*B + Al*B, fp32 accumulate)
//   out[32768, 512] = A @ W (+ epilogue)
// CTA 128(M) x 128(N), 8 warps (4x2), warp tile 32x64.
// K: 16 iterations of k32, 3-stage cp.async pipeline, 1 sync per iteration.
// __launch_bounds__(256, 2): cap regs at 128 so 2 CTAs co-reside per SM
// (16 warps) — one CTA's MMA phase hides the other's sync/load bubbles.
// EPI: 0 raw->out; 1 gate; 2 relu->fp16 split; 3 residual
// ---------------------------------------------------------------------------
#define SA_SZ 10240                           // 128 rows x 80B (64B data + 16 pad)
#define SB_SZ 8704                            // 32 rows x 272B (256B data + 16 pad)
#define SB_BASE (3 * 2 * SA_SZ)               // 61440
#define SM_TOT  (SB_BASE + 3 * SB_SZ)         // 87552 (x2 CTAs = 171KB < 228KB)

__device__ __forceinline__ void stage_cp(
    unsigned int smb, int slot, int kidx, int tid, int m0, int n0,
    const __half* __restrict__ Ah, const __half* __restrict__ Al,
    const __half* __restrict__ Bh)
{
    const int ko = kidx * 32;
    const unsigned int abase = smb + slot * 2 * SA_SZ;
    const unsigned int bbase = smb + SB_BASE + slot * SB_SZ;
#pragma unroll
    for (int i = 0; i < 2; ++i) {
        const int seg = tid + i * 256;          // 0..511
        const int row = seg >> 2, part = seg & 3;
        const unsigned int so = abase + row * 80 + part * 16;
        const size_t go = (size_t)(m0 + row) * H_ + ko + part * 8;
        cp16(so, Ah + go);
        cp16(so + SA_SZ, Al + go);
    }
#pragma unroll
    for (int i = 0; i < 2; ++i) {
        const int seg = tid + i * 256;          // 0..511
        const int row = seg >> 4, part = seg & 15;
        const unsigned int so = bbase + row * 272 + part * 16;
        const size_t go = (size_t)(ko + row) * H_ + n0 + part * 8;
        cp16(so, Bh + go);
    }
}

template<int EPI>
__global__ __launch_bounds__(256, 2) void gemm_tc(
    const __half* __restrict__ Ah, const __half* __restrict__ Al,
    const __half* __restrict__ Bh,
    const float* __restrict__ bias, float* __restrict__ out,
    float* __restrict__ aux, __half* __restrict__ outh,
    __half* __restrict__ outl)
{
    extern __shared__ char smem[];
    const unsigned int smb = smem_u32(smem);
    const int tid  = threadIdx.x;
    const int lane = tid & 31;
    const int warp = tid >> 5;
    const int wm   = (warp >> 1) * 32;
    const int wn   = (warp & 1) * 64;
    const int m0   = blockIdx.y * 128;
    const int n0   = blockIdx.x * 128;

    float acc[2][8][4];
#pragma unroll
    for (int i = 0; i < 2; ++i)
#pragma unroll
        for (int j = 0; j < 8; ++j)
#pragma unroll
            for (int l = 0; l < 4; ++l) acc[i][j][l] = 0.f;

    const int a_row_sel = lane & 15;
    const int a_k_sel   = (lane >> 4) * 8;
    const int b_k_sel   = lane & 15;
    const int b_n_sel   = (lane >> 4) * 8;

    stage_cp(smb, 0, 0, tid, m0, n0, Ah, Al, Bh); cp_commit();
    stage_cp(smb, 1, 1, tid, m0, n0, Ah, Al, Bh); cp_commit();

#pragma unroll 1
    for (int it = 0; it < 16; ++it) {
        cp_wait<1>();
        __syncthreads();
        if (it + 2 < 16) {
            stage_cp(smb, (it + 2) % 3, it + 2, tid, m0, n0, Ah, Al, Bh);
            cp_commit();
        }
        const int slot = it % 3;
        const unsigned int abase = smb + slot * 2 * SA_SZ;
        const unsigned int bbase = smb + SB_BASE + slot * SB_SZ;
#pragma unroll
        for (int ks = 0; ks < 2; ++ks) {
            unsigned int ah[2][4], al[2][4];
#pragma unroll
            for (int mi = 0; mi < 2; ++mi) {
                const unsigned int ad = abase +
                    ((wm + mi * 16 + a_row_sel) * 40 + ks * 16 + a_k_sel) * 2;
                ldsm_x4(ah[mi], ad);
                ldsm_x4(al[mi], ad + SA_SZ);
            }
            unsigned int bh[4][4];
#pragma unroll
            for (int nb = 0; nb < 4; ++nb) {
                const unsigned int bd = bbase +
                    ((ks * 16 + b_k_sel) * 136 + wn + nb * 16 + b_n_sel) * 2;
                ldsm_x4t(bh[nb], bd);
            }
            // term-major: 16x AhB, then 16x AlB (acc reuse distance 16)
#pragma unroll
            for (int mi = 0; mi < 2; ++mi)
#pragma unroll
                for (int nb = 0; nb < 4; ++nb) {
                    mma_f16(acc[mi][2 * nb + 0], ah[mi], &bh[nb][0]);
                    mma_f16(acc[mi][2 * nb + 1], ah[mi], &bh[nb][2]);
                }
#pragma unroll
            for (int mi = 0; mi < 2; ++mi)
#pragma unroll
                for (int nb = 0; nb < 4; ++nb) {
                    mma_f16(acc[mi][2 * nb + 0], al[mi], &bh[nb][0]);
                    mma_f16(acc[mi][2 * nb + 1], al[mi], &bh[nb][2]);
                }
        }
    }

    // epilogue
    const int group = lane >> 2;
    const int tig2  = (lane & 3) * 2;
#pragma unroll
    for (int mi = 0; mi < 2; ++mi) {
#pragma unroll
        for (int ni = 0; ni < 8; ++ni) {
            const int col = n0 + wn + ni * 8 + tig2;
            const float bx = bias[col], by = bias[col + 1];
#pragma unroll
            for (int half = 0; half < 2; ++half) {
                const int row = m0 + wm + mi * 16 + group + half * 8;
                const size_t o = (size_t)row * H_ + col;
                float rx = acc[mi][ni][half * 2 + 0] + bx;
                float ry = acc[mi][ni][half * 2 + 1] + by;
                if (EPI == 0) {
                    *(float2*)(out + o) = make_float2(rx, ry);
                } else if (EPI == 1) {
                    float2 k2 = *(const float2*)(aux + o);
                    float cx = 1.f / (1.f + expf(k2.x));
                    float cy = 1.f / (1.f + expf(k2.y));
                    float vx = (1.f - cx) * gfun(rx);
                    float vy = (1.f - cy) * gfun(ry);
                    *(float2*)(aux + o) = make_float2(cx, cy);
                    *(float2*)(out + o) = make_float2(vx, vy);
                } else if (EPI == 2) {
                    rx = fmaxf(rx, 0.f); ry = fmaxf(ry, 0.f);
                    __half h0,h1,l0,l1;
                    split_fp16(rx, h0, l0); split_fp16(ry, h1, l1);
                    *(__half2*)(outh + o) = __halves2half2(h0, h1);
                    *(__half2*)(outl + o) = __halves2half2(l0, l1);
                } else {
                    float2 x2 = *(const float2*)(aux + o);
                    *(float2*)(out + o) = make_float2(rx + x2.x, ry + x2.y);
                }
            }
        }
    }
}

// ---------------------------------------------------------------------------
// Chunked scan (unchanged, near its HBM roofline)
// ---------------------------------------------------------------------------
__global__ __launch_bounds__(512) void scan_phase1(
    const float* __restrict__ c, const float* __restrict__ v,
    float* __restrict__ Aout, float* __restrict__ Bout)
{
    const int h  = threadIdx.x;
    const int bj = blockIdx.x;
    const int b  = bj >> 6, j = bj & (NC_ - 1);
    size_t base = ((size_t)b * T_ + (size_t)j * CL_) * H_ + h;
    float A = 1.f, Bv = 0.f;
    for (int t = 0; t < CL_; ++t) {
        const float ct = c[base];
        const float vt = v[base];
        Bv = fmaf(ct, Bv, vt);
        A *= ct;
        base += H_;
    }
    Aout[bj * H_ + h] = A;
    Bout[bj * H_ + h] = Bv;
}

__global__ __launch_bounds__(512) void scan_phase2(
    const float* __restrict__ A, const float* __restrict__ Bv,
    float* __restrict__ hin)
{
    const int h = threadIdx.x;
    const int b = blockIdx.x;
    float hr = 0.5f;
#pragma unroll
    for (int j = 0; j < NC_; ++j) {
        const int idx = (b * NC_ + j) * H_ + h;
        hin[idx] = hr;
        hr = fmaf(A[idx], hr, Bv[idx]);
    }
}

__global__ __launch_bounds__(512) void scan_phase3(
    const float* __restrict__ c, const float* __restrict__ v,
    const float* __restrict__ hin, const float* __restrict__ x,
    float* __restrict__ x2)
{
    const int h  = threadIdx.x;
    const int bj = blockIdx.x;
    const int b  = bj >> 6, j = bj & (NC_ - 1);
    size_t base = ((size_t)b * T_ + (size_t)j * CL_) * H_ + h;
    float hr = hin[bj * H_ + h];
    for (int t = 0; t < CL_; ++t) {
        hr = fmaf(c[base], hr, v[base]);
        x2[base] = x[base] + hr;
        base += H_;
    }
}

// ---------------------------------------------------------------------------
// launch
// ---------------------------------------------------------------------------
extern "C" void kernel_launch(void* const* d_in, const int* in_sizes, int n_in,
                              void* d_out, int out_size)
{
    const float* x    = (const float*)d_in[0];
    const float* ln1g = (const float*)d_in[1];
    const float* ln1b = (const float*)d_in[2];
    const float* Wz   = (const float*)d_in[3];
    const float* bz   = (const float*)d_in[4];
    const float* Wh   = (const float*)d_in[5];
    const float* bh   = (const float*)d_in[6];
    const float* ln2g = (const float*)d_in[7];
    const float* ln2b = (const float*)d_in[8];
    const float* W1   = (const float*)d_in[9];
    const float* b1   = (const float*)d_in[10];
    const float* W2   = (const float*)d_in[11];
    const float* b2   = (const float*)d_in[12];
    float* out = (float*)d_out;

    float *p_k, *p_v, *p_x2, *p_A, *p_Bv, *p_hin;
    __half *p_ah, *p_al, *p_h1h, *p_h1l;
    __half *p_wz, *p_wh, *p_w1, *p_w2;
    cudaGetSymbolAddress((void**)&p_k,   g_k);
    cudaGetSymbolAddress((void**)&p_v,   g_v);
    cudaGetSymbolAddress((void**)&p_x2,  g_x2);
    cudaGetSymbolAddress((void**)&p_ah,  g_ah);
    cudaGetSymbolAddress((void**)&p_al,  g_al);
    cudaGetSymbolAddress((void**)&p_h1h, g_h1h);
    cudaGetSymbolAddress((void**)&p_h1l, g_h1l);
    cudaGetSymbolAddress((void**)&p_wz,  g_wz);
    cudaGetSymbolAddress((void**)&p_wh,  g_wh);
    cudaGetSymbolAddress((void**)&p_w1,  g_w1);
    cudaGetSymbolAddress((void**)&p_w2,  g_w2);
    cudaGetSymbolAddress((void**)&p_A,   g_A);
    cudaGetSymbolAddress((void**)&p_Bv,  g_Bv);
    cudaGetSymbolAddress((void**)&p_hin, g_hin);

    cudaFuncSetAttribute(gemm_tc<0>, cudaFuncAttributeMaxDynamicSharedMemorySize, SM_TOT);
    cudaFuncSetAttribute(gemm_tc<1>, cudaFuncAttributeMaxDynamicSharedMemorySize, SM_TOT);
    cudaFuncSetAttribute(gemm_tc<2>, cudaFuncAttributeMaxDynamicSharedMemorySize, SM_TOT);
    cudaFuncSetAttribute(gemm_tc<3>, cudaFuncAttributeMaxDynamicSharedMemorySize, SM_TOT);

    const dim3 ggrid(4, BT_ / 128);    // (N tiles, M tiles) = (4, 256)

    // one-shot batched weight convert (4 weights, one launch)
    wconv_kernel<<<1024, 256>>>(Wz, Wh, W1, W2, p_wz, p_wh, p_w1, p_w2);

    // LN1 -> split activations
    ln_split_kernel<<<BT_ / 8, 256>>>(x, ln1g, ln1b, p_ah, p_al);
    // k raw
    gemm_tc<0><<<ggrid, 256, SM_TOT>>>(p_ah, p_al, p_wz, bz, p_k, nullptr, nullptr, nullptr);
    // preh -> c (g_k), v (g_v)
    gemm_tc<1><<<ggrid, 256, SM_TOT>>>(p_ah, p_al, p_wh, bh, p_v, p_k, nullptr, nullptr);
    // scan + residual -> g_x2
    scan_phase1<<<B_ * NC_, H_>>>(p_k, p_v, p_A, p_Bv);
    scan_phase2<<<B_, H_>>>(p_A, p_Bv, p_hin);
    scan_phase3<<<B_ * NC_, H_>>>(p_k, p_v, p_hin, x, p_x2);
    // LN2 -> split activations
    ln_split_kernel<<<BT_ / 8, 256>>>(p_x2, ln2g, ln2b, p_ah, p_al);
    // FFN
    gemm_tc<2><<<ggrid, 256, SM_TOT>>>(p_ah, p_al, p_w1, b1, nullptr, nullptr, p_h1h, p_h1l);
    gemm_tc<3><<<ggrid, 256, SM_TOT>>>(p_h1h, p_h1l, p_w2, b2, out, p_x2, nullptr, nullptr);
}